// round 14
// baseline (speedup 1.0000x reference)
#include <cuda_runtime.h>
#include <cuda_bf16.h>
#include <math.h>
#include <stdint.h>

#define NN 100000
#define EE 1200000
#define CC 64
#define TOTE (EE + NN)
#define SCHUNK 1024
#define NB_SCAN ((NN + SCHUNK - 1) / SCHUNK)   // 98
#define GEMM_BLOCKS ((NN + 127) / 128)         // 782

// ---------------- scratch (device globals; no allocation allowed) ----------------
__device__ float g_h0a[NN * CC];
__device__ float g_h0r[NN * CC];
__device__ float g_hW[NN * CC];
__device__ float g_hW2[NN * CC];
__device__ float g_atom[NN * CC];
__device__ float g_rh[NN * CC];
__device__ float g_mol[NN * CC];
__device__ float g_as[NN];
__device__ float g_ad[NN];
__device__ float g_as2[NN];
__device__ float g_ad2[NN];

__device__ int g_degA[NN];
__device__ int g_offA[NN + 1];
__device__ int g_curA[NN];
__device__ int g_csrA[TOTE];

__device__ int g_degR[NN];
__device__ int g_offR[NN + 1];
__device__ int g_curR[NN];
__device__ int g_csrR[TOTE];

__device__ int g_bsum[2 * 128];
__device__ int g_boff[2 * 128];

// ================= mma.sync helpers =================
__device__ __forceinline__ uint32_t smem_u32(const void* p) {
    uint32_t a;
    asm("{ .reg .u64 t; cvta.to.shared.u64 t, %1; cvt.u32.u64 %0, t; }" : "=r"(a) : "l"(p));
    return a;
}

#define LDSM_X4(d, addr) asm volatile( \
    "ldmatrix.sync.aligned.m8n8.x4.shared.b16 {%0,%1,%2,%3}, [%4];" \
    : "=r"((d)[0]), "=r"((d)[1]), "=r"((d)[2]), "=r"((d)[3]) : "r"(addr))

#define MMA16816(c, a, b0, b1) asm volatile( \
    "mma.sync.aligned.m16n8k16.row.col.f32.bf16.bf16.f32 " \
    "{%0,%1,%2,%3}, {%4,%5,%6,%7}, {%8,%9}, {%0,%1,%2,%3};" \
    : "+f"((c)[0]), "+f"((c)[1]), "+f"((c)[2]), "+f"((c)[3]) \
    : "r"((a)[0]), "r"((a)[1]), "r"((a)[2]), "r"((a)[3]), "r"(b0), "r"(b1))

// ================= unified tensor-core GEMM =================
struct TcArgs {
    const float* A;
    const float* A2;      // phase-1 input (concat), else null
    const float* W;       // [K_total, 64] row-major
    const float* bias;
    const float* attS;
    const float* attD;
    float* out;
    float* as_;
    float* ad_;
    int mode;             // 1 bias, 2 leaky(0.01), 4 att, 8 two-phase
};

#define PITCH 136                    // bf16 elems per smem row (272 B, 16B skew)
#define SM_B_OFF (128 * PITCH * 2)   // 34816
#define SM_SC_OFF (SM_B_OFF + 64 * PITCH * 2)  // 52224
#define SM_DYN (SM_SC_OFF + 768)
#define FPITCH 68                    // fp32 stage pitch (272 B); 128*68*4 = 34816 = As region

// pack 4 floats -> (hi bf16 x4, lo bf16 x4) as two uint2-storable halves
__device__ __forceinline__ void cvt4(const float4& v, uint2& hi, uint2& lo) {
    __nv_bfloat162 h01 = __floats2bfloat162_rn(v.x, v.y);
    __nv_bfloat162 h23 = __floats2bfloat162_rn(v.z, v.w);
    float lx = v.x - __bfloat162float(h01.x);
    float ly = v.y - __bfloat162float(h01.y);
    float lz = v.z - __bfloat162float(h23.x);
    float lw = v.w - __bfloat162float(h23.y);
    __nv_bfloat162 l01 = __floats2bfloat162_rn(lx, ly);
    __nv_bfloat162 l23 = __floats2bfloat162_rn(lz, lw);
    hi.x = *(uint32_t*)&h01; hi.y = *(uint32_t*)&h23;
    lo.x = *(uint32_t*)&l01; lo.y = *(uint32_t*)&l23;
}

// 256 threads = 8 warps; each warp owns a 16-row M slice of the 128-row tile.
// min-blocks=2 caps regs at 128 so TWO blocks (16 warps) fit per SM.
__global__ void __launch_bounds__(256, 2) mma_gemm_kernel(TcArgs g0, TcArgs g1, int n) {
    extern __shared__ char dsm[];
    __nv_bfloat16* As = (__nv_bfloat16*)dsm;               // [128][PITCH], cols 0-63 hi, 64-127 lo
    __nv_bfloat16* Bs = (__nv_bfloat16*)(dsm + SM_B_OFF);  // [64 n][PITCH k], cols 0-63 hi, 64-127 lo
    float* sc_bias = (float*)(dsm + SM_SC_OFF);
    float* sc_attS = sc_bias + 64;
    float* sc_attD = sc_attS + 64;

    const TcArgs g = blockIdx.y ? g1 : g0;
    int tid = threadIdx.x;
    int w = tid >> 5;
    int lane = tid & 31;
    int row0 = blockIdx.x * 128;

    if (tid < 64) sc_bias[tid] = (g.mode & 1) ? g.bias[tid] : 0.f;
    else if (tid < 128 && (g.mode & 4)) { sc_attS[tid - 64] = g.attS[tid - 64]; sc_attD[tid - 64] = g.attD[tid - 64]; }

    float acc[8][4];
#pragma unroll
    for (int ni = 0; ni < 8; ni++)
#pragma unroll
        for (int k = 0; k < 4; k++) acc[ni][k] = 0.f;

    uint32_t As_u = smem_u32(As);
    uint32_t Bs_u = smem_u32(Bs);

    int a_row_local = lane & 15;
    int a_kofs = (lane >> 4) * 8;
    int b_n = (lane & 7) + ((lane >> 4) & 1) * 8;
    int b_kofs = ((lane >> 3) & 1) * 8;

    int nphase = (g.mode & 8) ? 2 : 1;
    for (int ph = 0; ph < nphase; ph++) {
        const float* Asrc = ph ? g.A2 : g.A;
        const float* Wsrc = g.W + ph * 64 * 64;
        if (ph) __syncthreads();

        // convert A: fp32 [128x64] -> bf16 hi(0:64) | lo(64:128), vectorized
        for (int i = tid; i < 128 * 16; i += 256) {
            int r = i >> 4, cq = (i & 15) * 4;
            int gr = row0 + r;
            float4 v = (gr < n) ? *(const float4*)(Asrc + gr * 64 + cq)
                                : make_float4(0.f, 0.f, 0.f, 0.f);
            uint2 hi, lo;
            cvt4(v, hi, lo);
            *(uint2*)(As + r * PITCH + cq) = hi;
            *(uint2*)(As + r * PITCH + 64 + cq) = lo;
        }
        // convert B: Bs[n][k] = hi(W[k][n]); Bs[n][64+k] = lo
        for (int i = tid; i < 64 * 16; i += 256) {
            int k = i >> 4, nq = (i & 15) * 4;
            float4 v = *(const float4*)(Wsrc + k * 64 + nq);
            uint2 hi, lo;
            cvt4(v, hi, lo);
            __nv_bfloat162 h01 = *(__nv_bfloat162*)&hi.x;
            __nv_bfloat162 h23 = *(__nv_bfloat162*)&hi.y;
            __nv_bfloat162 l01 = *(__nv_bfloat162*)&lo.x;
            __nv_bfloat162 l23 = *(__nv_bfloat162*)&lo.y;
            Bs[(nq + 0) * PITCH + k] = h01.x;
            Bs[(nq + 1) * PITCH + k] = h01.y;
            Bs[(nq + 2) * PITCH + k] = h23.x;
            Bs[(nq + 3) * PITCH + k] = h23.y;
            Bs[(nq + 0) * PITCH + 64 + k] = l01.x;
            Bs[(nq + 1) * PITCH + 64 + k] = l01.y;
            Bs[(nq + 2) * PITCH + 64 + k] = l23.x;
            Bs[(nq + 3) * PITCH + 64 + k] = l23.y;
        }
        __syncthreads();

        uint32_t a_addr = As_u + ((w * 16 + a_row_local) * PITCH + a_kofs) * 2;
        uint32_t b_base = Bs_u + (b_n * PITCH + b_kofs) * 2;

        // 4 k16 steps; per step load A_hi/A_lo once and per-nb B_hi/B_lo once,
        // then issue hi*hi + lo*hi + hi*lo from registers (lo*lo omitted, ~2^-18)
#pragma unroll
        for (int s = 0; s < 4; s++) {
            uint32_t hi_koff = (uint32_t)(s * 16) * 2;
            uint32_t lo_koff = (uint32_t)(64 + s * 16) * 2;
            uint32_t a_hi[4], a_lo[4];
            LDSM_X4(a_hi, a_addr + hi_koff);
            LDSM_X4(a_lo, a_addr + lo_koff);
#pragma unroll
            for (int nb = 0; nb < 4; nb++) {
                uint32_t b_off = b_base + (uint32_t)(nb * 16 * PITCH) * 2;
                uint32_t b_hi[4], b_lo[4];
                LDSM_X4(b_hi, b_off + hi_koff);
                LDSM_X4(b_lo, b_off + lo_koff);
                MMA16816(acc[nb * 2 + 0], a_hi, b_hi[0], b_hi[1]);
                MMA16816(acc[nb * 2 + 1], a_hi, b_hi[2], b_hi[3]);
                MMA16816(acc[nb * 2 + 0], a_lo, b_hi[0], b_hi[1]);
                MMA16816(acc[nb * 2 + 1], a_lo, b_hi[2], b_hi[3]);
                MMA16816(acc[nb * 2 + 0], a_hi, b_lo[0], b_lo[1]);
                MMA16816(acc[nb * 2 + 1], a_hi, b_lo[2], b_lo[3]);
            }
        }
    }

    // ---- epilogue: compute in fragments, stage via smem, coalesced STG ----
    __syncthreads();  // all warps done reading As/Bs; reuse As region as fp32 stage
    float* stage = (float*)dsm;  // [128][FPITCH]
    int q = lane & 3;
    int rsub = lane >> 2;
#pragma unroll
    for (int half = 0; half < 2; half++) {
        int rl = w * 16 + rsub + half * 8;
        int r = row0 + rl;
        float s = 0.f, d = 0.f;
#pragma unroll
        for (int ni = 0; ni < 8; ni++) {
            int c = ni * 8 + q * 2;
            float v0 = acc[ni][half * 2 + 0] + sc_bias[c];
            float v1 = acc[ni][half * 2 + 1] + sc_bias[c + 1];
            if (g.mode & 2) {
                v0 = (v0 >= 0.f) ? v0 : 0.01f * v0;
                v1 = (v1 >= 0.f) ? v1 : 0.01f * v1;
            }
            if (g.mode & 4) {
                s += v0 * sc_attS[c] + v1 * sc_attS[c + 1];
                d += v0 * sc_attD[c] + v1 * sc_attD[c + 1];
            }
            float2 st = {v0, v1};
            *(float2*)(stage + rl * FPITCH + c) = st;
        }
        if (g.mode & 4) {
            s += __shfl_xor_sync(0xffffffffu, s, 1);
            s += __shfl_xor_sync(0xffffffffu, s, 2);
            d += __shfl_xor_sync(0xffffffffu, d, 1);
            d += __shfl_xor_sync(0xffffffffu, d, 2);
            if (q == 0 && r < n) { g.as_[r] = s; g.ad_[r] = d; }
        }
    }
    __syncthreads();
    // coalesced store: 128 rows x 16 float4
    for (int i = tid; i < 128 * 16; i += 256) {
        int r = i >> 4, cq = (i & 15) * 4;
        int gr = row0 + r;
        if (gr < n)
            *(float4*)(g.out + gr * 64 + cq) = *(const float4*)(stage + r * FPITCH + cq);
    }
}

// ================= CSR build (merged: blockIdx.y selects graph) =================
__global__ void init_deg_kernel(int* degA, int* degR) {
    int i = blockIdx.x * blockDim.x + threadIdx.x;
    int* deg = blockIdx.y ? degR : degA;
    if (i < NN) deg[i] = 1;  // self loop
}
__global__ void count_kernel(const int* dstA, const int* dstR, int* degA, int* degR) {
    int i = blockIdx.x * blockDim.x + threadIdx.x;
    const int* dst = blockIdx.y ? dstR : dstA;
    int* deg = blockIdx.y ? degR : degA;
    if (i < EE) atomicAdd(&deg[dst[i]], 1);
}
__global__ void block_sum_kernel(const int* degA, const int* degR, int* bsum) {
    __shared__ int sh[8];
    const int* deg = blockIdx.y ? degR : degA;
    int base = blockIdx.x * SCHUNK;
    int tid = threadIdx.x;
    int s = 0;
    for (int i = tid; i < SCHUNK; i += 256) {
        int idx = base + i;
        if (idx < NN) s += deg[idx];
    }
#pragma unroll
    for (int o = 16; o; o >>= 1) s += __shfl_xor_sync(0xffffffffu, s, o);
    if ((tid & 31) == 0) sh[tid >> 5] = s;
    __syncthreads();
    if (tid == 0) {
        int t = 0;
#pragma unroll
        for (int k = 0; k < 8; k++) t += sh[k];
        bsum[blockIdx.y * 128 + blockIdx.x] = t;
    }
}
__global__ void scan_sums_kernel(const int* bsum, int* boff, int* offA, int* offR) {
    __shared__ int sh[128];
    int y = blockIdx.x;
    int tid = threadIdx.x;
    int v = (tid < NB_SCAN) ? bsum[y * 128 + tid] : 0;
    sh[tid] = v;
    __syncthreads();
    for (int o = 1; o < 128; o <<= 1) {
        int t = (tid >= o) ? sh[tid - o] : 0;
        __syncthreads();
        sh[tid] += t;
        __syncthreads();
    }
    if (tid < NB_SCAN) boff[y * 128 + tid] = sh[tid] - v;
    if (tid == 127) (y ? offR : offA)[NN] = sh[127];
}
// scan_apply + fill_self merged
__global__ void scan_apply_kernel(const int* degA, const int* degR, const int* boff,
                                  int* offA, int* offR, int* curA, int* curR,
                                  int* csrA, int* csrR) {
    __shared__ int wsum[8];
    const int* deg = blockIdx.y ? degR : degA;
    int* off = blockIdx.y ? offR : offA;
    int* cursor = blockIdx.y ? curR : curA;
    int* csr = blockIdx.y ? csrR : csrA;
    int tid = threadIdx.x;
    int lane = tid & 31, w = tid >> 5;
    int base = blockIdx.x * SCHUNK + tid * 4;
    int v[4];
    int s = 0;
#pragma unroll
    for (int k = 0; k < 4; k++) {
        v[k] = (base + k < NN) ? deg[base + k] : 0;
        s += v[k];
    }
    int ps = s;
#pragma unroll
    for (int o = 1; o < 32; o <<= 1) {
        int t = __shfl_up_sync(0xffffffffu, ps, o);
        if (lane >= o) ps += t;
    }
    if (lane == 31) wsum[w] = ps;
    __syncthreads();
    if (tid == 0) {
        int c = 0;
#pragma unroll
        for (int k = 0; k < 8; k++) { int t = wsum[k]; wsum[k] = c; c += t; }
    }
    __syncthreads();
    int run = boff[blockIdx.y * 128 + blockIdx.x] + wsum[w] + ps - s;
#pragma unroll
    for (int k = 0; k < 4; k++) {
        int i = base + k;
        if (i < NN) {
            off[i] = run;
            csr[run] = i;          // self loop occupies slot 0
            cursor[i] = run + 1;
        }
        run += v[k];
    }
}
__global__ void scatter_kernel(const int* srcA, const int* dstA, const int* srcR, const int* dstR,
                               int* curA, int* curR, int* csrA, int* csrR) {
    int i = blockIdx.x * blockDim.x + threadIdx.x;
    const int* src = blockIdx.y ? srcR : srcA;
    const int* dst = blockIdx.y ? dstR : dstA;
    int* cursor = blockIdx.y ? curR : curA;
    int* csr = blockIdx.y ? csrR : csrA;
    if (i < EE) {
        int p = atomicAdd(&cursor[dst[i]], 1);
        csr[p] = src[i];
    }
}

// ================= GAT aggregation (R5 best variant: dynamic inner loop) =================
struct AggArgs {
    const int* off;
    const int* csr;
    const float* hW;
    const float* as_;
    const float* ad_;
    const float* bias;
    float* out;
};
__global__ void gat_aggregate_kernel(AggArgs a0, AggArgs a1) {
    const AggArgs a = blockIdx.y ? a1 : a0;
    int warp = (blockIdx.x * blockDim.x + threadIdx.x) >> 5;
    int lane = threadIdx.x & 31;
    if (warp >= NN) return;
    int start = a.off[warp];
    int end = a.off[warp + 1];
    float adi = a.ad_[warp];

    float s = 0.f, acc0 = 0.f, acc1 = 0.f;
    for (int base = start; base < end; base += 32) {
        int j = base + lane;
        int sidx = 0;
        float ex = 0.f;
        if (j < end) {
            sidx = a.csr[j];
            float e = a.as_[sidx] + adi;
            e = (e >= 0.f) ? e : 0.2f * e;
            ex = __expf(e);
        }
        s += ex;
        int cnt = min(32, end - base);
        for (int t = 0; t < cnt; t++) {
            int ss = __shfl_sync(0xffffffffu, sidx, t);
            float w = __shfl_sync(0xffffffffu, ex, t);
            float2 v = *(const float2*)(a.hW + ss * 64 + 2 * lane);
            acc0 += w * v.x;
            acc1 += w * v.y;
        }
    }
#pragma unroll
    for (int o = 16; o; o >>= 1) s += __shfl_xor_sync(0xffffffffu, s, o);
    float inv = 1.f / (s + 1e-16f);

    float2 r;
    r.x = acc0 * inv + a.bias[2 * lane];
    r.y = acc1 * inv + a.bias[2 * lane + 1];
    *(float2*)(a.out + warp * 64 + 2 * lane) = r;
}

// ================= host launcher =================
extern "C" void kernel_launch(void* const* d_in, const int* in_sizes, int n_in,
                              void* d_out, int out_size) {
    const float* x       = (const float*)d_in[0];
    const int*   ei      = (const int*)d_in[1];
    const float* rg_x    = (const float*)d_in[3];
    const int*   rei     = (const int*)d_in[4];
    const float* W1      = (const float*)d_in[6];
    const float* b1      = (const float*)d_in[7];
    const float* atom_W  = (const float*)d_in[8];
    const float* atom_as = (const float*)d_in[9];
    const float* atom_ad = (const float*)d_in[10];
    const float* atom_b  = (const float*)d_in[11];
    const float* rg_W    = (const float*)d_in[12];
    const float* rg_as   = (const float*)d_in[13];
    const float* rg_ad   = (const float*)d_in[14];
    const float* rg_b    = (const float*)d_in[15];
    const float* mol_W   = (const float*)d_in[16];
    const float* mol_as  = (const float*)d_in[17];
    const float* mol_ad  = (const float*)d_in[18];
    const float* mol_b   = (const float*)d_in[19];
    const float* W2      = (const float*)d_in[20];
    const float* b2      = (const float*)d_in[21];
    float* out = (float*)d_out;

    const int* srcA = ei;
    const int* dstA = ei + EE;
    const int* srcR = rei;
    const int* dstR = rei + EE;

    float *h0a, *h0r, *hW, *hW2, *atomo, *rh, *mol, *as_, *ad_, *as2, *ad2;
    int *degA, *offA, *curA, *csrA, *degR, *offR, *curR, *csrR, *bsum, *boff;
    cudaGetSymbolAddress((void**)&h0a, g_h0a);
    cudaGetSymbolAddress((void**)&h0r, g_h0r);
    cudaGetSymbolAddress((void**)&hW, g_hW);
    cudaGetSymbolAddress((void**)&hW2, g_hW2);
    cudaGetSymbolAddress((void**)&atomo, g_atom);
    cudaGetSymbolAddress((void**)&rh, g_rh);
    cudaGetSymbolAddress((void**)&mol, g_mol);
    cudaGetSymbolAddress((void**)&as_, g_as);
    cudaGetSymbolAddress((void**)&ad_, g_ad);
    cudaGetSymbolAddress((void**)&as2, g_as2);
    cudaGetSymbolAddress((void**)&ad2, g_ad2);
    cudaGetSymbolAddress((void**)&degA, g_degA);
    cudaGetSymbolAddress((void**)&offA, g_offA);
    cudaGetSymbolAddress((void**)&curA, g_curA);
    cudaGetSymbolAddress((void**)&csrA, g_csrA);
    cudaGetSymbolAddress((void**)&degR, g_degR);
    cudaGetSymbolAddress((void**)&offR, g_offR);
    cudaGetSymbolAddress((void**)&curR, g_curR);
    cudaGetSymbolAddress((void**)&csrR, g_csrR);
    cudaGetSymbolAddress((void**)&bsum, g_bsum);
    cudaGetSymbolAddress((void**)&boff, g_boff);

    cudaFuncSetAttribute(mma_gemm_kernel, cudaFuncAttributeMaxDynamicSharedMemorySize, SM_DYN);

    const int WB = (NN * 32 + 255) / 256;

    // CSR build (both graphs per launch); lin1 gemm interleaved at launch index 3
    init_deg_kernel<<<dim3((NN + 255) / 256, 2), 256>>>(degA, degR);
    count_kernel<<<dim3((EE + 255) / 256, 2), 256>>>(dstA, dstR, degA, degR);
    block_sum_kernel<<<dim3(NB_SCAN, 2), 256>>>(degA, degR, bsum);

    // lin1 both graphs (no CSR dependency) — positioned here so ncu captures it
    TcArgs l0 = {x,    nullptr, W1, b1, nullptr, nullptr, h0a, nullptr, nullptr, 3};
    TcArgs l1 = {rg_x, nullptr, W1, b1, nullptr, nullptr, h0r, nullptr, nullptr, 3};
    mma_gemm_kernel<<<dim3(GEMM_BLOCKS, 2), 256, SM_DYN>>>(l0, l1, NN);

    scan_sums_kernel<<<2, 128>>>(bsum, boff, offA, offR);
    scan_apply_kernel<<<dim3(NB_SCAN, 2), 256>>>(degA, degR, boff, offA, offR,
                                                 curA, curR, csrA, csrR);
    scatter_kernel<<<dim3((EE + 255) / 256, 2), 256>>>(srcA, dstA, srcR, dstR, curA, curR, csrA, csrR);

    // atom + rg conv gemm (mode = att)
    TcArgs c0 = {h0a, nullptr, atom_W, nullptr, atom_as, atom_ad, hW,  as_, ad_, 4};
    TcArgs c1 = {h0r, nullptr, rg_W,   nullptr, rg_as,   rg_ad,   hW2, as2, ad2, 4};
    mma_gemm_kernel<<<dim3(GEMM_BLOCKS, 2), 256, SM_DYN>>>(c0, c1, NN);

    // atom + rg aggregation
    AggArgs a0 = {offA, csrA, hW,  as_, ad_, atom_b, atomo};
    AggArgs a1 = {offR, csrR, hW2, as2, ad2, rg_b,   rh};
    gat_aggregate_kernel<<<dim3(WB, 2), 256>>>(a0, a1);

    // mol conv gemm
    TcArgs m0 = {atomo, nullptr, mol_W, nullptr, mol_as, mol_ad, hW, as_, ad_, 4};
    mma_gemm_kernel<<<dim3(GEMM_BLOCKS, 1), 256, SM_DYN>>>(m0, m0, NN);

    // mol aggregation
    AggArgs am = {offA, csrA, hW, as_, ad_, mol_b, mol};
    gat_aggregate_kernel<<<dim3(WB, 1), 256>>>(am, am);

    // final: out = concat(mol, rh) @ W2 + b2 (two-phase, bias)
    TcArgs f0 = {mol, rh, W2, b2, nullptr, nullptr, out, nullptr, nullptr, 1 | 8};
    mma_gemm_kernel<<<dim3(GEMM_BLOCKS, 1), 256, SM_DYN>>>(f0, f0, NN);
}

// round 15
// speedup vs baseline: 1.0282x; 1.0282x over previous
#include <cuda_runtime.h>
#include <cuda_bf16.h>
#include <math.h>
#include <stdint.h>

#define NN 100000
#define EE 1200000
#define CC 64
#define TOTE (EE + NN)
#define SCHUNK 1024
#define NB_SCAN ((NN + SCHUNK - 1) / SCHUNK)   // 98
#define GEMM_BLOCKS ((NN + 127) / 128)         // 782

// ---------------- scratch (device globals; no allocation allowed) ----------------
__device__ float g_h0a[NN * CC];
__device__ float g_h0r[NN * CC];
__device__ float g_hW[NN * CC];
__device__ float g_hW2[NN * CC];
__device__ float g_atom[NN * CC];
__device__ float g_rh[NN * CC];
__device__ float g_mol[NN * CC];
__device__ float g_as[NN];
__device__ float g_ad[NN];
__device__ float g_as2[NN];
__device__ float g_ad2[NN];

__device__ int g_degA[NN];
__device__ int g_offA[NN + 1];
__device__ int g_curA[NN];
__device__ int g_csrA[TOTE];

__device__ int g_degR[NN];
__device__ int g_offR[NN + 1];
__device__ int g_curR[NN];
__device__ int g_csrR[TOTE];

__device__ int g_bsum[2 * 128];
__device__ int g_boff[2 * 128];

// ================= mma.sync helpers =================
__device__ __forceinline__ uint32_t smem_u32(const void* p) {
    uint32_t a;
    asm("{ .reg .u64 t; cvta.to.shared.u64 t, %1; cvt.u32.u64 %0, t; }" : "=r"(a) : "l"(p));
    return a;
}

#define LDSM_X4(d, addr) asm volatile( \
    "ldmatrix.sync.aligned.m8n8.x4.shared.b16 {%0,%1,%2,%3}, [%4];" \
    : "=r"((d)[0]), "=r"((d)[1]), "=r"((d)[2]), "=r"((d)[3]) : "r"(addr))

#define MMA16816(c, a, b0, b1) asm volatile( \
    "mma.sync.aligned.m16n8k16.row.col.f32.bf16.bf16.f32 " \
    "{%0,%1,%2,%3}, {%4,%5,%6,%7}, {%8,%9}, {%0,%1,%2,%3};" \
    : "+f"((c)[0]), "+f"((c)[1]), "+f"((c)[2]), "+f"((c)[3]) \
    : "r"((a)[0]), "r"((a)[1]), "r"((a)[2]), "r"((a)[3]), "r"(b0), "r"(b1))

// ================= unified tensor-core GEMM =================
struct TcArgs {
    const float* A;
    const float* A2;      // phase-1 input (concat), else null
    const float* W;       // [K_total, 64] row-major
    const float* bias;
    const float* attS;
    const float* attD;
    float* out;
    float* as_;
    float* ad_;
    int mode;             // 1 bias, 2 leaky(0.01), 4 att, 8 two-phase
};

#define PITCH 136                    // bf16 elems per smem row (272 B, 16B skew)
#define SM_B_OFF (128 * PITCH * 2)   // 34816
#define SM_SC_OFF (SM_B_OFF + 64 * PITCH * 2)  // 52224
#define SM_DYN (SM_SC_OFF + 768)

// pack 4 floats -> (hi bf16 x4, lo bf16 x4) as two uint2-storable halves
__device__ __forceinline__ void cvt4(const float4& v, uint2& hi, uint2& lo) {
    __nv_bfloat162 h01 = __floats2bfloat162_rn(v.x, v.y);
    __nv_bfloat162 h23 = __floats2bfloat162_rn(v.z, v.w);
    float lx = v.x - __bfloat162float(h01.x);
    float ly = v.y - __bfloat162float(h01.y);
    float lz = v.z - __bfloat162float(h23.x);
    float lw = v.w - __bfloat162float(h23.y);
    __nv_bfloat162 l01 = __floats2bfloat162_rn(lx, ly);
    __nv_bfloat162 l23 = __floats2bfloat162_rn(lz, lw);
    hi.x = *(uint32_t*)&h01; hi.y = *(uint32_t*)&h23;
    lo.x = *(uint32_t*)&l01; lo.y = *(uint32_t*)&l23;
}

// 256 threads = 8 warps; each warp owns a 16-row M slice of the 128-row tile.
// min-blocks=2 caps regs at 128 so TWO blocks (16 warps) fit per SM.
__global__ void __launch_bounds__(256, 2) mma_gemm_kernel(TcArgs g0, TcArgs g1, int n) {
    extern __shared__ char dsm[];
    __nv_bfloat16* As = (__nv_bfloat16*)dsm;               // [128][PITCH], cols 0-63 hi, 64-127 lo
    __nv_bfloat16* Bs = (__nv_bfloat16*)(dsm + SM_B_OFF);  // [64 n][PITCH k], cols 0-63 hi, 64-127 lo
    float* sc_bias = (float*)(dsm + SM_SC_OFF);
    float* sc_attS = sc_bias + 64;
    float* sc_attD = sc_attS + 64;

    const TcArgs g = blockIdx.y ? g1 : g0;
    int tid = threadIdx.x;
    int w = tid >> 5;
    int lane = tid & 31;
    int row0 = blockIdx.x * 128;

    if (tid < 64) sc_bias[tid] = (g.mode & 1) ? g.bias[tid] : 0.f;
    else if (tid < 128 && (g.mode & 4)) { sc_attS[tid - 64] = g.attS[tid - 64]; sc_attD[tid - 64] = g.attD[tid - 64]; }

    float acc[8][4];
#pragma unroll
    for (int ni = 0; ni < 8; ni++)
#pragma unroll
        for (int k = 0; k < 4; k++) acc[ni][k] = 0.f;

    uint32_t As_u = smem_u32(As);
    uint32_t Bs_u = smem_u32(Bs);

    int a_row_local = lane & 15;
    int a_kofs = (lane >> 4) * 8;
    int b_n = (lane & 7) + ((lane >> 4) & 1) * 8;
    int b_kofs = ((lane >> 3) & 1) * 8;

    int nphase = (g.mode & 8) ? 2 : 1;
    for (int ph = 0; ph < nphase; ph++) {
        const float* Asrc = ph ? g.A2 : g.A;
        const float* Wsrc = g.W + ph * 64 * 64;
        if (ph) __syncthreads();

        // convert A: fp32 [128x64] -> bf16 hi(0:64) | lo(64:128), vectorized
        for (int i = tid; i < 128 * 16; i += 256) {
            int r = i >> 4, cq = (i & 15) * 4;
            int gr = row0 + r;
            float4 v = (gr < n) ? *(const float4*)(Asrc + gr * 64 + cq)
                                : make_float4(0.f, 0.f, 0.f, 0.f);
            uint2 hi, lo;
            cvt4(v, hi, lo);
            *(uint2*)(As + r * PITCH + cq) = hi;
            *(uint2*)(As + r * PITCH + 64 + cq) = lo;
        }
        // convert B: Bs[n][k] = hi(W[k][n]); Bs[n][64+k] = lo
        for (int i = tid; i < 64 * 16; i += 256) {
            int k = i >> 4, nq = (i & 15) * 4;
            float4 v = *(const float4*)(Wsrc + k * 64 + nq);
            uint2 hi, lo;
            cvt4(v, hi, lo);
            __nv_bfloat162 h01 = *(__nv_bfloat162*)&hi.x;
            __nv_bfloat162 h23 = *(__nv_bfloat162*)&hi.y;
            __nv_bfloat162 l01 = *(__nv_bfloat162*)&lo.x;
            __nv_bfloat162 l23 = *(__nv_bfloat162*)&lo.y;
            Bs[(nq + 0) * PITCH + k] = h01.x;
            Bs[(nq + 1) * PITCH + k] = h01.y;
            Bs[(nq + 2) * PITCH + k] = h23.x;
            Bs[(nq + 3) * PITCH + k] = h23.y;
            Bs[(nq + 0) * PITCH + 64 + k] = l01.x;
            Bs[(nq + 1) * PITCH + 64 + k] = l01.y;
            Bs[(nq + 2) * PITCH + 64 + k] = l23.x;
            Bs[(nq + 3) * PITCH + 64 + k] = l23.y;
        }
        __syncthreads();

        uint32_t a_addr = As_u + ((w * 16 + a_row_local) * PITCH + a_kofs) * 2;
        uint32_t b_base = Bs_u + (b_n * PITCH + b_kofs) * 2;

        // 4 k16 steps; per step load A_hi/A_lo once and per-nb B_hi/B_lo once,
        // then issue hi*hi + lo*hi + hi*lo from registers (lo*lo omitted, ~2^-18)
#pragma unroll
        for (int s = 0; s < 4; s++) {
            uint32_t hi_koff = (uint32_t)(s * 16) * 2;
            uint32_t lo_koff = (uint32_t)(64 + s * 16) * 2;
            uint32_t a_hi[4], a_lo[4];
            LDSM_X4(a_hi, a_addr + hi_koff);
            LDSM_X4(a_lo, a_addr + lo_koff);
#pragma unroll
            for (int nb = 0; nb < 4; nb++) {
                uint32_t b_off = b_base + (uint32_t)(nb * 16 * PITCH) * 2;
                uint32_t b_hi[4], b_lo[4];
                LDSM_X4(b_hi, b_off + hi_koff);
                LDSM_X4(b_lo, b_off + lo_koff);
                MMA16816(acc[nb * 2 + 0], a_hi, b_hi[0], b_hi[1]);
                MMA16816(acc[nb * 2 + 1], a_hi, b_hi[2], b_hi[3]);
                MMA16816(acc[nb * 2 + 0], a_lo, b_hi[0], b_hi[1]);
                MMA16816(acc[nb * 2 + 1], a_lo, b_hi[2], b_hi[3]);
                MMA16816(acc[nb * 2 + 0], a_hi, b_lo[0], b_lo[1]);
                MMA16816(acc[nb * 2 + 1], a_hi, b_lo[2], b_lo[3]);
            }
        }
    }

    // ---- epilogue straight from fragments (R13 best variant) ----
    int q = lane & 3;
    int rsub = lane >> 2;
#pragma unroll
    for (int half = 0; half < 2; half++) {
        int r = row0 + w * 16 + rsub + half * 8;
        float s = 0.f, d = 0.f;
#pragma unroll
        for (int ni = 0; ni < 8; ni++) {
            int c = ni * 8 + q * 2;
            float v0 = acc[ni][half * 2 + 0] + sc_bias[c];
            float v1 = acc[ni][half * 2 + 1] + sc_bias[c + 1];
            if (g.mode & 2) {
                v0 = (v0 >= 0.f) ? v0 : 0.01f * v0;
                v1 = (v1 >= 0.f) ? v1 : 0.01f * v1;
            }
            if (g.mode & 4) {
                s += v0 * sc_attS[c] + v1 * sc_attS[c + 1];
                d += v0 * sc_attD[c] + v1 * sc_attD[c + 1];
            }
            if (r < n) {
                float2 st = {v0, v1};
                *(float2*)(g.out + r * 64 + c) = st;
            }
        }
        if (g.mode & 4) {
            s += __shfl_xor_sync(0xffffffffu, s, 1);
            s += __shfl_xor_sync(0xffffffffu, s, 2);
            d += __shfl_xor_sync(0xffffffffu, d, 1);
            d += __shfl_xor_sync(0xffffffffu, d, 2);
            if (q == 0 && r < n) { g.as_[r] = s; g.ad_[r] = d; }
        }
    }
}

// ================= CSR build (merged: blockIdx.y selects graph) =================
__global__ void init_deg_kernel(int* degA, int* degR) {
    int i = blockIdx.x * blockDim.x + threadIdx.x;
    int* deg = blockIdx.y ? degR : degA;
    if (i < NN) deg[i] = 1;  // self loop
}
__global__ void count_kernel(const int* dstA, const int* dstR, int* degA, int* degR) {
    int i = blockIdx.x * blockDim.x + threadIdx.x;
    const int* dst = blockIdx.y ? dstR : dstA;
    int* deg = blockIdx.y ? degR : degA;
    if (i < EE) atomicAdd(&deg[dst[i]], 1);
}
__global__ void block_sum_kernel(const int* degA, const int* degR, int* bsum) {
    __shared__ int sh[8];
    const int* deg = blockIdx.y ? degR : degA;
    int base = blockIdx.x * SCHUNK;
    int tid = threadIdx.x;
    int s = 0;
    for (int i = tid; i < SCHUNK; i += 256) {
        int idx = base + i;
        if (idx < NN) s += deg[idx];
    }
#pragma unroll
    for (int o = 16; o; o >>= 1) s += __shfl_xor_sync(0xffffffffu, s, o);
    if ((tid & 31) == 0) sh[tid >> 5] = s;
    __syncthreads();
    if (tid == 0) {
        int t = 0;
#pragma unroll
        for (int k = 0; k < 8; k++) t += sh[k];
        bsum[blockIdx.y * 128 + blockIdx.x] = t;
    }
}
__global__ void scan_sums_kernel(const int* bsum, int* boff, int* offA, int* offR) {
    __shared__ int sh[128];
    int y = blockIdx.x;
    int tid = threadIdx.x;
    int v = (tid < NB_SCAN) ? bsum[y * 128 + tid] : 0;
    sh[tid] = v;
    __syncthreads();
    for (int o = 1; o < 128; o <<= 1) {
        int t = (tid >= o) ? sh[tid - o] : 0;
        __syncthreads();
        sh[tid] += t;
        __syncthreads();
    }
    if (tid < NB_SCAN) boff[y * 128 + tid] = sh[tid] - v;
    if (tid == 127) (y ? offR : offA)[NN] = sh[127];
}
// scan_apply + fill_self merged
__global__ void scan_apply_kernel(const int* degA, const int* degR, const int* boff,
                                  int* offA, int* offR, int* curA, int* curR,
                                  int* csrA, int* csrR) {
    __shared__ int wsum[8];
    const int* deg = blockIdx.y ? degR : degA;
    int* off = blockIdx.y ? offR : offA;
    int* cursor = blockIdx.y ? curR : curA;
    int* csr = blockIdx.y ? csrR : csrA;
    int tid = threadIdx.x;
    int lane = tid & 31, w = tid >> 5;
    int base = blockIdx.x * SCHUNK + tid * 4;
    int v[4];
    int s = 0;
#pragma unroll
    for (int k = 0; k < 4; k++) {
        v[k] = (base + k < NN) ? deg[base + k] : 0;
        s += v[k];
    }
    int ps = s;
#pragma unroll
    for (int o = 1; o < 32; o <<= 1) {
        int t = __shfl_up_sync(0xffffffffu, ps, o);
        if (lane >= o) ps += t;
    }
    if (lane == 31) wsum[w] = ps;
    __syncthreads();
    if (tid == 0) {
        int c = 0;
#pragma unroll
        for (int k = 0; k < 8; k++) { int t = wsum[k]; wsum[k] = c; c += t; }
    }
    __syncthreads();
    int run = boff[blockIdx.y * 128 + blockIdx.x] + wsum[w] + ps - s;
#pragma unroll
    for (int k = 0; k < 4; k++) {
        int i = base + k;
        if (i < NN) {
            off[i] = run;
            csr[run] = i;          // self loop occupies slot 0
            cursor[i] = run + 1;
        }
        run += v[k];
    }
}
__global__ void scatter_kernel(const int* srcA, const int* dstA, const int* srcR, const int* dstR,
                               int* curA, int* curR, int* csrA, int* csrR) {
    int i = blockIdx.x * blockDim.x + threadIdx.x;
    const int* src = blockIdx.y ? srcR : srcA;
    const int* dst = blockIdx.y ? dstR : dstA;
    int* cursor = blockIdx.y ? curR : curA;
    int* csr = blockIdx.y ? csrR : csrA;
    if (i < EE) {
        int p = atomicAdd(&cursor[dst[i]], 1);
        csr[p] = src[i];
    }
}

// ================= GAT aggregation (dynamic inner loop + partial unroll 4) =================
struct AggArgs {
    const int* off;
    const int* csr;
    const float* hW;
    const float* as_;
    const float* ad_;
    const float* bias;
    float* out;
};
__global__ void gat_aggregate_kernel(AggArgs a0, AggArgs a1) {
    const AggArgs a = blockIdx.y ? a1 : a0;
    int warp = (blockIdx.x * blockDim.x + threadIdx.x) >> 5;
    int lane = threadIdx.x & 31;
    if (warp >= NN) return;
    int start = a.off[warp];
    int end = a.off[warp + 1];
    float adi = a.ad_[warp];

    float s = 0.f, acc0 = 0.f, acc1 = 0.f;
    for (int base = start; base < end; base += 32) {
        int j = base + lane;
        int sidx = 0;
        float ex = 0.f;
        if (j < end) {
            sidx = a.csr[j];
            float e = a.as_[sidx] + adi;
            e = (e >= 0.f) ? e : 0.2f * e;
            ex = __expf(e);
        }
        s += ex;
        int cnt = min(32, end - base);
#pragma unroll 4
        for (int t = 0; t < cnt; t++) {
            int ss = __shfl_sync(0xffffffffu, sidx, t);
            float w = __shfl_sync(0xffffffffu, ex, t);
            float2 v = *(const float2*)(a.hW + ss * 64 + 2 * lane);
            acc0 += w * v.x;
            acc1 += w * v.y;
        }
    }
#pragma unroll
    for (int o = 16; o; o >>= 1) s += __shfl_xor_sync(0xffffffffu, s, o);
    float inv = 1.f / (s + 1e-16f);

    float2 r;
    r.x = acc0 * inv + a.bias[2 * lane];
    r.y = acc1 * inv + a.bias[2 * lane + 1];
    *(float2*)(a.out + warp * 64 + 2 * lane) = r;
}

// ================= host launcher =================
extern "C" void kernel_launch(void* const* d_in, const int* in_sizes, int n_in,
                              void* d_out, int out_size) {
    const float* x       = (const float*)d_in[0];
    const int*   ei      = (const int*)d_in[1];
    const float* rg_x    = (const float*)d_in[3];
    const int*   rei     = (const int*)d_in[4];
    const float* W1      = (const float*)d_in[6];
    const float* b1      = (const float*)d_in[7];
    const float* atom_W  = (const float*)d_in[8];
    const float* atom_as = (const float*)d_in[9];
    const float* atom_ad = (const float*)d_in[10];
    const float* atom_b  = (const float*)d_in[11];
    const float* rg_W    = (const float*)d_in[12];
    const float* rg_as   = (const float*)d_in[13];
    const float* rg_ad   = (const float*)d_in[14];
    const float* rg_b    = (const float*)d_in[15];
    const float* mol_W   = (const float*)d_in[16];
    const float* mol_as  = (const float*)d_in[17];
    const float* mol_ad  = (const float*)d_in[18];
    const float* mol_b   = (const float*)d_in[19];
    const float* W2      = (const float*)d_in[20];
    const float* b2      = (const float*)d_in[21];
    float* out = (float*)d_out;

    const int* srcA = ei;
    const int* dstA = ei + EE;
    const int* srcR = rei;
    const int* dstR = rei + EE;

    float *h0a, *h0r, *hW, *hW2, *atomo, *rh, *mol, *as_, *ad_, *as2, *ad2;
    int *degA, *offA, *curA, *csrA, *degR, *offR, *curR, *csrR, *bsum, *boff;
    cudaGetSymbolAddress((void**)&h0a, g_h0a);
    cudaGetSymbolAddress((void**)&h0r, g_h0r);
    cudaGetSymbolAddress((void**)&hW, g_hW);
    cudaGetSymbolAddress((void**)&hW2, g_hW2);
    cudaGetSymbolAddress((void**)&atomo, g_atom);
    cudaGetSymbolAddress((void**)&rh, g_rh);
    cudaGetSymbolAddress((void**)&mol, g_mol);
    cudaGetSymbolAddress((void**)&as_, g_as);
    cudaGetSymbolAddress((void**)&ad_, g_ad);
    cudaGetSymbolAddress((void**)&as2, g_as2);
    cudaGetSymbolAddress((void**)&ad2, g_ad2);
    cudaGetSymbolAddress((void**)&degA, g_degA);
    cudaGetSymbolAddress((void**)&offA, g_offA);
    cudaGetSymbolAddress((void**)&curA, g_curA);
    cudaGetSymbolAddress((void**)&csrA, g_csrA);
    cudaGetSymbolAddress((void**)&degR, g_degR);
    cudaGetSymbolAddress((void**)&offR, g_offR);
    cudaGetSymbolAddress((void**)&curR, g_curR);
    cudaGetSymbolAddress((void**)&csrR, g_csrR);
    cudaGetSymbolAddress((void**)&bsum, g_bsum);
    cudaGetSymbolAddress((void**)&boff, g_boff);

    cudaFuncSetAttribute(mma_gemm_kernel, cudaFuncAttributeMaxDynamicSharedMemorySize, SM_DYN);

    const int WB = (NN * 32 + 255) / 256;

    // CSR build (both graphs per launch); lin1 gemm interleaved at launch index 3
    init_deg_kernel<<<dim3((NN + 255) / 256, 2), 256>>>(degA, degR);
    count_kernel<<<dim3((EE + 255) / 256, 2), 256>>>(dstA, dstR, degA, degR);
    block_sum_kernel<<<dim3(NB_SCAN, 2), 256>>>(degA, degR, bsum);

    // lin1 both graphs (no CSR dependency) — positioned here so ncu captures it
    TcArgs l0 = {x,    nullptr, W1, b1, nullptr, nullptr, h0a, nullptr, nullptr, 3};
    TcArgs l1 = {rg_x, nullptr, W1, b1, nullptr, nullptr, h0r, nullptr, nullptr, 3};
    mma_gemm_kernel<<<dim3(GEMM_BLOCKS, 2), 256, SM_DYN>>>(l0, l1, NN);

    scan_sums_kernel<<<2, 128>>>(bsum, boff, offA, offR);
    scan_apply_kernel<<<dim3(NB_SCAN, 2), 256>>>(degA, degR, boff, offA, offR,
                                                 curA, curR, csrA, csrR);
    scatter_kernel<<<dim3((EE + 255) / 256, 2), 256>>>(srcA, dstA, srcR, dstR, curA, curR, csrA, csrR);

    // atom + rg conv gemm (mode = att)
    TcArgs c0 = {h0a, nullptr, atom_W, nullptr, atom_as, atom_ad, hW,  as_, ad_, 4};
    TcArgs c1 = {h0r, nullptr, rg_W,   nullptr, rg_as,   rg_ad,   hW2, as2, ad2, 4};
    mma_gemm_kernel<<<dim3(GEMM_BLOCKS, 2), 256, SM_DYN>>>(c0, c1, NN);

    // atom + rg aggregation
    AggArgs a0 = {offA, csrA, hW,  as_, ad_, atom_b, atomo};
    AggArgs a1 = {offR, csrR, hW2, as2, ad2, rg_b,   rh};
    gat_aggregate_kernel<<<dim3(WB, 2), 256>>>(a0, a1);

    // mol conv gemm
    TcArgs m0 = {atomo, nullptr, mol_W, nullptr, mol_as, mol_ad, hW, as_, ad_, 4};
    mma_gemm_kernel<<<dim3(GEMM_BLOCKS, 1), 256, SM_DYN>>>(m0, m0, NN);

    // mol aggregation
    AggArgs am = {offA, csrA, hW, as_, ad_, mol_b, mol};
    gat_aggregate_kernel<<<dim3(WB, 1), 256>>>(am, am);

    // final: out = concat(mol, rh) @ W2 + b2 (two-phase, bias)
    TcArgs f0 = {mol, rh, W2, b2, nullptr, nullptr, out, nullptr, nullptr, 1 | 8};
    mma_gemm_kernel<<<dim3(GEMM_BLOCKS, 1), 256, SM_DYN>>>(f0, f0, NN);
}

// round 16
// speedup vs baseline: 1.0612x; 1.0321x over previous
#include <cuda_runtime.h>
#include <cuda_bf16.h>
#include <math.h>
#include <stdint.h>

#define NN 100000
#define EE 1200000
#define CC 64
#define TOTE (EE + NN)
#define SCHUNK 1024
#define NB_SCAN ((NN + SCHUNK - 1) / SCHUNK)   // 98
#define GEMM_BLOCKS ((NN + 127) / 128)         // 782

// ---------------- scratch (device globals; no allocation allowed) ----------------
__device__ float g_hW[NN * CC];
__device__ float g_hW2[NN * CC];
__device__ float g_atom[NN * CC];
__device__ float g_rh[NN * CC];
__device__ float g_mol[NN * CC];
__device__ float g_as[NN];
__device__ float g_ad[NN];
__device__ float g_as2[NN];
__device__ float g_ad2[NN];

__device__ int g_degA[NN];
__device__ int g_offA[NN + 1];
__device__ int g_curA[NN];
__device__ int g_csrA[TOTE];

__device__ int g_degR[NN];
__device__ int g_offR[NN + 1];
__device__ int g_curR[NN];
__device__ int g_csrR[TOTE];

__device__ int g_bsum[2 * 128];
__device__ int g_boff[2 * 128];

// ================= mma.sync helpers =================
__device__ __forceinline__ uint32_t smem_u32(const void* p) {
    uint32_t a;
    asm("{ .reg .u64 t; cvta.to.shared.u64 t, %1; cvt.u32.u64 %0, t; }" : "=r"(a) : "l"(p));
    return a;
}

#define LDSM_X4(d, addr) asm volatile( \
    "ldmatrix.sync.aligned.m8n8.x4.shared.b16 {%0,%1,%2,%3}, [%4];" \
    : "=r"((d)[0]), "=r"((d)[1]), "=r"((d)[2]), "=r"((d)[3]) : "r"(addr))

#define MMA16816(c, a, b0, b1) asm volatile( \
    "mma.sync.aligned.m16n8k16.row.col.f32.bf16.bf16.f32 " \
    "{%0,%1,%2,%3}, {%4,%5,%6,%7}, {%8,%9}, {%0,%1,%2,%3};" \
    : "+f"((c)[0]), "+f"((c)[1]), "+f"((c)[2]), "+f"((c)[3]) \
    : "r"((a)[0]), "r"((a)[1]), "r"((a)[2]), "r"((a)[3]), "r"(b0), "r"(b1))

#define PITCH 136                    // bf16 elems per smem row (272 B, 16B skew)
#define SM_B_OFF (128 * PITCH * 2)   // 34816
#define SM_SC_OFF (SM_B_OFF + 64 * PITCH * 2)  // 52224
#define SM_DYN (SM_SC_OFF + 768)

// pack 4 floats -> (hi bf16 x4, lo bf16 x4) as two uint2-storable halves
__device__ __forceinline__ void cvt4(const float4& v, uint2& hi, uint2& lo) {
    __nv_bfloat162 h01 = __floats2bfloat162_rn(v.x, v.y);
    __nv_bfloat162 h23 = __floats2bfloat162_rn(v.z, v.w);
    float lx = v.x - __bfloat162float(h01.x);
    float ly = v.y - __bfloat162float(h01.y);
    float lz = v.z - __bfloat162float(h23.x);
    float lw = v.w - __bfloat162float(h23.y);
    __nv_bfloat162 l01 = __floats2bfloat162_rn(lx, ly);
    __nv_bfloat162 l23 = __floats2bfloat162_rn(lz, lw);
    hi.x = *(uint32_t*)&h01; hi.y = *(uint32_t*)&h23;
    lo.x = *(uint32_t*)&l01; lo.y = *(uint32_t*)&l23;
}

// shared device helpers for the mainloop phases
struct SmemCtx {
    char* dsm;
    uint32_t As_u, Bs_u;
};

__device__ __forceinline__ void convert_A_tile(char* dsm, const float* Asrc, int row0, int n, int tid) {
    __nv_bfloat16* As = (__nv_bfloat16*)dsm;
    for (int i = tid; i < 128 * 16; i += 256) {
        int r = i >> 4, cq = (i & 15) * 4;
        int gr = row0 + r;
        float4 v = (gr < n) ? *(const float4*)(Asrc + gr * 64 + cq)
                            : make_float4(0.f, 0.f, 0.f, 0.f);
        uint2 hi, lo;
        cvt4(v, hi, lo);
        *(uint2*)(As + r * PITCH + cq) = hi;
        *(uint2*)(As + r * PITCH + 64 + cq) = lo;
    }
}

__device__ __forceinline__ void convert_B_tile(char* dsm, const float* Wsrc, int tid) {
    __nv_bfloat16* Bs = (__nv_bfloat16*)(dsm + SM_B_OFF);
    for (int i = tid; i < 64 * 16; i += 256) {
        int k = i >> 4, nq = (i & 15) * 4;
        float4 v = *(const float4*)(Wsrc + k * 64 + nq);
        uint2 hi, lo;
        cvt4(v, hi, lo);
        __nv_bfloat162 h01 = *(__nv_bfloat162*)&hi.x;
        __nv_bfloat162 h23 = *(__nv_bfloat162*)&hi.y;
        __nv_bfloat162 l01 = *(__nv_bfloat162*)&lo.x;
        __nv_bfloat162 l23 = *(__nv_bfloat162*)&lo.y;
        Bs[(nq + 0) * PITCH + k] = h01.x;
        Bs[(nq + 1) * PITCH + k] = h01.y;
        Bs[(nq + 2) * PITCH + k] = h23.x;
        Bs[(nq + 3) * PITCH + k] = h23.y;
        Bs[(nq + 0) * PITCH + 64 + k] = l01.x;
        Bs[(nq + 1) * PITCH + 64 + k] = l01.y;
        Bs[(nq + 2) * PITCH + 64 + k] = l23.x;
        Bs[(nq + 3) * PITCH + 64 + k] = l23.y;
    }
}

// 4 k16 steps; per step load A_hi/A_lo once and per-nb B_hi/B_lo once,
// then issue hi*hi + lo*hi + hi*lo from registers (lo*lo omitted, ~2^-18)
__device__ __forceinline__ void run_mainloop(float (&acc)[8][4], uint32_t a_addr, uint32_t b_base) {
#pragma unroll
    for (int s = 0; s < 4; s++) {
        uint32_t hi_koff = (uint32_t)(s * 16) * 2;
        uint32_t lo_koff = (uint32_t)(64 + s * 16) * 2;
        uint32_t a_hi[4], a_lo[4];
        LDSM_X4(a_hi, a_addr + hi_koff);
        LDSM_X4(a_lo, a_addr + lo_koff);
#pragma unroll
        for (int nb = 0; nb < 4; nb++) {
            uint32_t b_off = b_base + (uint32_t)(nb * 16 * PITCH) * 2;
            uint32_t b_hi[4], b_lo[4];
            LDSM_X4(b_hi, b_off + hi_koff);
            LDSM_X4(b_lo, b_off + lo_koff);
            MMA16816(acc[nb * 2 + 0], a_hi, b_hi[0], b_hi[1]);
            MMA16816(acc[nb * 2 + 1], a_hi, b_hi[2], b_hi[3]);
            MMA16816(acc[nb * 2 + 0], a_lo, b_hi[0], b_hi[1]);
            MMA16816(acc[nb * 2 + 1], a_lo, b_hi[2], b_hi[3]);
            MMA16816(acc[nb * 2 + 0], a_hi, b_lo[0], b_lo[1]);
            MMA16816(acc[nb * 2 + 1], a_hi, b_lo[2], b_lo[3]);
        }
    }
}

// ================= general tensor-core GEMM (mol conv + final concat) =================
struct TcArgs {
    const float* A;
    const float* A2;      // phase-1 input (concat), else null
    const float* W;       // [K_total, 64] row-major
    const float* bias;
    const float* attS;
    const float* attD;
    float* out;
    float* as_;
    float* ad_;
    int mode;             // 1 bias, 4 att, 8 two-phase
};

__global__ void __launch_bounds__(256, 2) mma_gemm_kernel(TcArgs g0, TcArgs g1, int n) {
    extern __shared__ char dsm[];
    float* sc_bias = (float*)(dsm + SM_SC_OFF);
    float* sc_attS = sc_bias + 64;
    float* sc_attD = sc_attS + 64;

    const TcArgs g = blockIdx.y ? g1 : g0;
    int tid = threadIdx.x;
    int w = tid >> 5;
    int lane = tid & 31;
    int row0 = blockIdx.x * 128;

    if (tid < 64) sc_bias[tid] = (g.mode & 1) ? g.bias[tid] : 0.f;
    else if (tid < 128 && (g.mode & 4)) { sc_attS[tid - 64] = g.attS[tid - 64]; sc_attD[tid - 64] = g.attD[tid - 64]; }

    float acc[8][4];
#pragma unroll
    for (int ni = 0; ni < 8; ni++)
#pragma unroll
        for (int k = 0; k < 4; k++) acc[ni][k] = 0.f;

    uint32_t As_u = smem_u32(dsm);
    uint32_t Bs_u = smem_u32(dsm + SM_B_OFF);

    int a_row_local = lane & 15;
    int a_kofs = (lane >> 4) * 8;
    int b_n = (lane & 7) + ((lane >> 4) & 1) * 8;
    int b_kofs = ((lane >> 3) & 1) * 8;

    uint32_t a_addr = As_u + ((w * 16 + a_row_local) * PITCH + a_kofs) * 2;
    uint32_t b_base = Bs_u + (b_n * PITCH + b_kofs) * 2;

    int nphase = (g.mode & 8) ? 2 : 1;
    for (int ph = 0; ph < nphase; ph++) {
        const float* Asrc = ph ? g.A2 : g.A;
        const float* Wsrc = g.W + ph * 64 * 64;
        if (ph) __syncthreads();
        convert_A_tile(dsm, Asrc, row0, n, tid);
        convert_B_tile(dsm, Wsrc, tid);
        __syncthreads();
        run_mainloop(acc, a_addr, b_base);
    }

    // ---- epilogue straight from fragments ----
    int q = lane & 3;
    int rsub = lane >> 2;
#pragma unroll
    for (int half = 0; half < 2; half++) {
        int r = row0 + w * 16 + rsub + half * 8;
        float s = 0.f, d = 0.f;
#pragma unroll
        for (int ni = 0; ni < 8; ni++) {
            int c = ni * 8 + q * 2;
            float v0 = acc[ni][half * 2 + 0] + sc_bias[c];
            float v1 = acc[ni][half * 2 + 1] + sc_bias[c + 1];
            if (g.mode & 4) {
                s += v0 * sc_attS[c] + v1 * sc_attS[c + 1];
                d += v0 * sc_attD[c] + v1 * sc_attD[c + 1];
            }
            if (r < n) {
                float2 st = {v0, v1};
                *(float2*)(g.out + r * 64 + c) = st;
            }
        }
        if (g.mode & 4) {
            s += __shfl_xor_sync(0xffffffffu, s, 1);
            s += __shfl_xor_sync(0xffffffffu, s, 2);
            d += __shfl_xor_sync(0xffffffffu, d, 1);
            d += __shfl_xor_sync(0xffffffffu, d, 2);
            if (q == 0 && r < n) { g.as_[r] = s; g.ad_[r] = d; }
        }
    }
}

// ================= fused lin1 + conv GEMM (dedicated kernel) =================
// hW = (leaky(x@W1 + b1)) @ Wc ; as_/ad_ = att dots of hW rows
struct FusedArgs {
    const float* x;
    const float* W1;
    const float* b1;
    const float* Wc;
    const float* attS;
    const float* attD;
    float* out;
    float* as_;
    float* ad_;
};

__global__ void __launch_bounds__(256, 2) mma_fused_kernel(FusedArgs g0, FusedArgs g1, int n) {
    extern __shared__ char dsm[];
    __nv_bfloat16* As = (__nv_bfloat16*)dsm;
    float* sc_bias = (float*)(dsm + SM_SC_OFF);
    float* sc_attS = sc_bias + 64;
    float* sc_attD = sc_attS + 64;

    const FusedArgs g = blockIdx.y ? g1 : g0;
    int tid = threadIdx.x;
    int w = tid >> 5;
    int lane = tid & 31;
    int row0 = blockIdx.x * 128;

    if (tid < 64) sc_bias[tid] = g.b1[tid];
    else if (tid < 128) { sc_attS[tid - 64] = g.attS[tid - 64]; sc_attD[tid - 64] = g.attD[tid - 64]; }

    float acc[8][4];
#pragma unroll
    for (int ni = 0; ni < 8; ni++)
#pragma unroll
        for (int k = 0; k < 4; k++) acc[ni][k] = 0.f;

    uint32_t As_u = smem_u32(dsm);
    uint32_t Bs_u = smem_u32(dsm + SM_B_OFF);

    int a_row_local = lane & 15;
    int a_kofs = (lane >> 4) * 8;
    int b_n = (lane & 7) + ((lane >> 4) & 1) * 8;
    int b_kofs = ((lane >> 3) & 1) * 8;
    int q = lane & 3;
    int rsub = lane >> 2;

    uint32_t a_addr = As_u + ((w * 16 + a_row_local) * PITCH + a_kofs) * 2;
    uint32_t b_base = Bs_u + (b_n * PITCH + b_kofs) * 2;

    // --- phase 1: x @ W1 ---
    convert_A_tile(dsm, g.x, row0, n, tid);
    convert_B_tile(dsm, g.W1, tid);
    __syncthreads();
    run_mainloop(acc, a_addr, b_base);

    // --- mid epilogue: v = leaky(acc + b1); re-split into As as hi/lo; zero acc ---
    __syncthreads();  // all warps done reading As/Bs
#pragma unroll
    for (int half = 0; half < 2; half++) {
        int rl = w * 16 + rsub + half * 8;
#pragma unroll
        for (int ni = 0; ni < 8; ni++) {
            int c = ni * 8 + q * 2;
            float v0 = acc[ni][half * 2 + 0] + sc_bias[c];
            float v1 = acc[ni][half * 2 + 1] + sc_bias[c + 1];
            v0 = (v0 >= 0.f) ? v0 : 0.01f * v0;
            v1 = (v1 >= 0.f) ? v1 : 0.01f * v1;
            __nv_bfloat162 hi = __floats2bfloat162_rn(v0, v1);
            float l0 = v0 - __bfloat162float(hi.x);
            float l1 = v1 - __bfloat162float(hi.y);
            __nv_bfloat162 lo = __floats2bfloat162_rn(l0, l1);
            *(__nv_bfloat162*)(As + rl * PITCH + c) = hi;
            *(__nv_bfloat162*)(As + rl * PITCH + 64 + c) = lo;
            acc[ni][half * 2 + 0] = 0.f;
            acc[ni][half * 2 + 1] = 0.f;
        }
    }
    convert_B_tile(dsm, g.Wc, tid);
    __syncthreads();

    // --- phase 2: h @ Wc ---
    run_mainloop(acc, a_addr, b_base);

    // --- final epilogue: store hW + att dots (no bias/act) ---
#pragma unroll
    for (int half = 0; half < 2; half++) {
        int r = row0 + w * 16 + rsub + half * 8;
        float s = 0.f, d = 0.f;
#pragma unroll
        for (int ni = 0; ni < 8; ni++) {
            int c = ni * 8 + q * 2;
            float v0 = acc[ni][half * 2 + 0];
            float v1 = acc[ni][half * 2 + 1];
            s += v0 * sc_attS[c] + v1 * sc_attS[c + 1];
            d += v0 * sc_attD[c] + v1 * sc_attD[c + 1];
            if (r < n) {
                float2 st = {v0, v1};
                *(float2*)(g.out + r * 64 + c) = st;
            }
        }
        s += __shfl_xor_sync(0xffffffffu, s, 1);
        s += __shfl_xor_sync(0xffffffffu, s, 2);
        d += __shfl_xor_sync(0xffffffffu, d, 1);
        d += __shfl_xor_sync(0xffffffffu, d, 2);
        if (q == 0 && r < n) { g.as_[r] = s; g.ad_[r] = d; }
    }
}

// ================= CSR build (merged: blockIdx.y selects graph) =================
__global__ void init_deg_kernel(int* degA, int* degR) {
    int i = blockIdx.x * blockDim.x + threadIdx.x;
    int* deg = blockIdx.y ? degR : degA;
    if (i < NN) deg[i] = 1;  // self loop
}
__global__ void count_kernel(const int* dstA, const int* dstR, int* degA, int* degR) {
    int i = blockIdx.x * blockDim.x + threadIdx.x;
    const int* dst = blockIdx.y ? dstR : dstA;
    int* deg = blockIdx.y ? degR : degA;
    if (i < EE) atomicAdd(&deg[dst[i]], 1);
}
__global__ void block_sum_kernel(const int* degA, const int* degR, int* bsum) {
    __shared__ int sh[8];
    const int* deg = blockIdx.y ? degR : degA;
    int base = blockIdx.x * SCHUNK;
    int tid = threadIdx.x;
    int s = 0;
    for (int i = tid; i < SCHUNK; i += 256) {
        int idx = base + i;
        if (idx < NN) s += deg[idx];
    }
#pragma unroll
    for (int o = 16; o; o >>= 1) s += __shfl_xor_sync(0xffffffffu, s, o);
    if ((tid & 31) == 0) sh[tid >> 5] = s;
    __syncthreads();
    if (tid == 0) {
        int t = 0;
#pragma unroll
        for (int k = 0; k < 8; k++) t += sh[k];
        bsum[blockIdx.y * 128 + blockIdx.x] = t;
    }
}
__global__ void scan_sums_kernel(const int* bsum, int* boff, int* offA, int* offR) {
    __shared__ int sh[128];
    int y = blockIdx.x;
    int tid = threadIdx.x;
    int v = (tid < NB_SCAN) ? bsum[y * 128 + tid] : 0;
    sh[tid] = v;
    __syncthreads();
    for (int o = 1; o < 128; o <<= 1) {
        int t = (tid >= o) ? sh[tid - o] : 0;
        __syncthreads();
        sh[tid] += t;
        __syncthreads();
    }
    if (tid < NB_SCAN) boff[y * 128 + tid] = sh[tid] - v;
    if (tid == 127) (y ? offR : offA)[NN] = sh[127];
}
// scan_apply + fill_self merged
__global__ void scan_apply_kernel(const int* degA, const int* degR, const int* boff,
                                  int* offA, int* offR, int* curA, int* curR,
                                  int* csrA, int* csrR) {
    __shared__ int wsum[8];
    const int* deg = blockIdx.y ? degR : degA;
    int* off = blockIdx.y ? offR : offA;
    int* cursor = blockIdx.y ? curR : curA;
    int* csr = blockIdx.y ? csrR : csrA;
    int tid = threadIdx.x;
    int lane = tid & 31, w = tid >> 5;
    int base = blockIdx.x * SCHUNK + tid * 4;
    int v[4];
    int s = 0;
#pragma unroll
    for (int k = 0; k < 4; k++) {
        v[k] = (base + k < NN) ? deg[base + k] : 0;
        s += v[k];
    }
    int ps = s;
#pragma unroll
    for (int o = 1; o < 32; o <<= 1) {
        int t = __shfl_up_sync(0xffffffffu, ps, o);
        if (lane >= o) ps += t;
    }
    if (lane == 31) wsum[w] = ps;
    __syncthreads();
    if (tid == 0) {
        int c = 0;
#pragma unroll
        for (int k = 0; k < 8; k++) { int t = wsum[k]; wsum[k] = c; c += t; }
    }
    __syncthreads();
    int run = boff[blockIdx.y * 128 + blockIdx.x] + wsum[w] + ps - s;
#pragma unroll
    for (int k = 0; k < 4; k++) {
        int i = base + k;
        if (i < NN) {
            off[i] = run;
            csr[run] = i;          // self loop occupies slot 0
            cursor[i] = run + 1;
        }
        run += v[k];
    }
}
__global__ void scatter_kernel(const int* srcA, const int* dstA, const int* srcR, const int* dstR,
                               int* curA, int* curR, int* csrA, int* csrR) {
    int i = blockIdx.x * blockDim.x + threadIdx.x;
    const int* src = blockIdx.y ? srcR : srcA;
    const int* dst = blockIdx.y ? dstR : dstA;
    int* cursor = blockIdx.y ? curR : curA;
    int* csr = blockIdx.y ? csrR : csrA;
    if (i < EE) {
        int p = atomicAdd(&cursor[dst[i]], 1);
        csr[p] = src[i];
    }
}

// ================= GAT aggregation (R13 best variant: dynamic inner loop) =================
struct AggArgs {
    const int* off;
    const int* csr;
    const float* hW;
    const float* as_;
    const float* ad_;
    const float* bias;
    float* out;
};
__global__ void gat_aggregate_kernel(AggArgs a0, AggArgs a1) {
    const AggArgs a = blockIdx.y ? a1 : a0;
    int warp = (blockIdx.x * blockDim.x + threadIdx.x) >> 5;
    int lane = threadIdx.x & 31;
    if (warp >= NN) return;
    int start = a.off[warp];
    int end = a.off[warp + 1];
    float adi = a.ad_[warp];

    float s = 0.f, acc0 = 0.f, acc1 = 0.f;
    for (int base = start; base < end; base += 32) {
        int j = base + lane;
        int sidx = 0;
        float ex = 0.f;
        if (j < end) {
            sidx = a.csr[j];
            float e = a.as_[sidx] + adi;
            e = (e >= 0.f) ? e : 0.2f * e;
            ex = __expf(e);
        }
        s += ex;
        int cnt = min(32, end - base);
        for (int t = 0; t < cnt; t++) {
            int ss = __shfl_sync(0xffffffffu, sidx, t);
            float w = __shfl_sync(0xffffffffu, ex, t);
            float2 v = *(const float2*)(a.hW + ss * 64 + 2 * lane);
            acc0 += w * v.x;
            acc1 += w * v.y;
        }
    }
#pragma unroll
    for (int o = 16; o; o >>= 1) s += __shfl_xor_sync(0xffffffffu, s, o);
    float inv = 1.f / (s + 1e-16f);

    float2 r;
    r.x = acc0 * inv + a.bias[2 * lane];
    r.y = acc1 * inv + a.bias[2 * lane + 1];
    *(float2*)(a.out + warp * 64 + 2 * lane) = r;
}

// ================= host launcher =================
extern "C" void kernel_launch(void* const* d_in, const int* in_sizes, int n_in,
                              void* d_out, int out_size) {
    const float* x       = (const float*)d_in[0];
    const int*   ei      = (const int*)d_in[1];
    const float* rg_x    = (const float*)d_in[3];
    const int*   rei     = (const int*)d_in[4];
    const float* W1      = (const float*)d_in[6];
    const float* b1      = (const float*)d_in[7];
    const float* atom_W  = (const float*)d_in[8];
    const float* atom_as = (const float*)d_in[9];
    const float* atom_ad = (const float*)d_in[10];
    const float* atom_b  = (const float*)d_in[11];
    const float* rg_W    = (const float*)d_in[12];
    const float* rg_as   = (const float*)d_in[13];
    const float* rg_ad   = (const float*)d_in[14];
    const float* rg_b    = (const float*)d_in[15];
    const float* mol_W   = (const float*)d_in[16];
    const float* mol_as  = (const float*)d_in[17];
    const float* mol_ad  = (const float*)d_in[18];
    const float* mol_b   = (const float*)d_in[19];
    const float* W2      = (const float*)d_in[20];
    const float* b2      = (const float*)d_in[21];
    float* out = (float*)d_out;

    const int* srcA = ei;
    const int* dstA = ei + EE;
    const int* srcR = rei;
    const int* dstR = rei + EE;

    float *hW, *hW2, *atomo, *rh, *mol, *as_, *ad_, *as2, *ad2;
    int *degA, *offA, *curA, *csrA, *degR, *offR, *curR, *csrR, *bsum, *boff;
    cudaGetSymbolAddress((void**)&hW, g_hW);
    cudaGetSymbolAddress((void**)&hW2, g_hW2);
    cudaGetSymbolAddress((void**)&atomo, g_atom);
    cudaGetSymbolAddress((void**)&rh, g_rh);
    cudaGetSymbolAddress((void**)&mol, g_mol);
    cudaGetSymbolAddress((void**)&as_, g_as);
    cudaGetSymbolAddress((void**)&ad_, g_ad);
    cudaGetSymbolAddress((void**)&as2, g_as2);
    cudaGetSymbolAddress((void**)&ad2, g_ad2);
    cudaGetSymbolAddress((void**)&degA, g_degA);
    cudaGetSymbolAddress((void**)&offA, g_offA);
    cudaGetSymbolAddress((void**)&curA, g_curA);
    cudaGetSymbolAddress((void**)&csrA, g_csrA);
    cudaGetSymbolAddress((void**)&degR, g_degR);
    cudaGetSymbolAddress((void**)&offR, g_offR);
    cudaGetSymbolAddress((void**)&curR, g_curR);
    cudaGetSymbolAddress((void**)&csrR, g_csrR);
    cudaGetSymbolAddress((void**)&bsum, g_bsum);
    cudaGetSymbolAddress((void**)&boff, g_boff);

    cudaFuncSetAttribute(mma_gemm_kernel, cudaFuncAttributeMaxDynamicSharedMemorySize, SM_DYN);
    cudaFuncSetAttribute(mma_fused_kernel, cudaFuncAttributeMaxDynamicSharedMemorySize, SM_DYN);

    const int WB = (NN * 32 + 255) / 256;

    // CSR build (both graphs per launch); fused gemm interleaved at launch index 3
    init_deg_kernel<<<dim3((NN + 255) / 256, 2), 256>>>(degA, degR);
    count_kernel<<<dim3((EE + 255) / 256, 2), 256>>>(dstA, dstR, degA, degR);
    block_sum_kernel<<<dim3(NB_SCAN, 2), 256>>>(degA, degR, bsum);

    // fused lin1 + conv for both graphs (no CSR dependency)
    FusedArgs f0a = {x,    W1, b1, atom_W, atom_as, atom_ad, hW,  as_, ad_};
    FusedArgs f1a = {rg_x, W1, b1, rg_W,   rg_as,   rg_ad,   hW2, as2, ad2};
    mma_fused_kernel<<<dim3(GEMM_BLOCKS, 2), 256, SM_DYN>>>(f0a, f1a, NN);

    scan_sums_kernel<<<2, 128>>>(bsum, boff, offA, offR);
    scan_apply_kernel<<<dim3(NB_SCAN, 2), 256>>>(degA, degR, boff, offA, offR,
                                                 curA, curR, csrA, csrR);
    scatter_kernel<<<dim3((EE + 255) / 256, 2), 256>>>(srcA, dstA, srcR, dstR, curA, curR, csrA, csrR);

    // atom + rg aggregation
    AggArgs a0 = {offA, csrA, hW,  as_, ad_, atom_b, atomo};
    AggArgs a1 = {offR, csrR, hW2, as2, ad2, rg_b,   rh};
    gat_aggregate_kernel<<<dim3(WB, 2), 256>>>(a0, a1);

    // mol conv gemm
    TcArgs m0 = {atomo, nullptr, mol_W, nullptr, mol_as, mol_ad, hW, as_, ad_, 4};
    mma_gemm_kernel<<<dim3(GEMM_BLOCKS, 1), 256, SM_DYN>>>(m0, m0, NN);

    // mol aggregation
    AggArgs am = {offA, csrA, hW, as_, ad_, mol_b, mol};
    gat_aggregate_kernel<<<dim3(WB, 1), 256>>>(am, am);

    // final: out = concat(mol, rh) @ W2 + b2 (two-phase, bias)
    TcArgs ff = {mol, rh, W2, b2, nullptr, nullptr, out, nullptr, nullptr, 1 | 8};
    mma_gemm_kernel<<<dim3(GEMM_BLOCKS, 1), 256, SM_DYN>>>(ff, ff, NN);
}

// round 17
// speedup vs baseline: 1.0745x; 1.0126x over previous
#include <cuda_runtime.h>
#include <cuda_bf16.h>
#include <math.h>
#include <stdint.h>

#define NN 100000
#define EE 1200000
#define CC 64
#define TOTE (EE + NN)
#define SCHUNK 1024
#define NB_SCAN ((NN + SCHUNK - 1) / SCHUNK)   // 98
#define GEMM_BLOCKS ((NN + 127) / 128)         // 782

// ---------------- scratch (device globals; no allocation allowed) ----------------
__device__ float g_hW[NN * CC];
__device__ float g_hW2[NN * CC];
__device__ float g_atom[NN * CC];
__device__ float g_rh[NN * CC];
__device__ float g_mol[NN * CC];
__device__ float g_as[NN];
__device__ float g_ad[NN];
__device__ float g_as2[NN];
__device__ float g_ad2[NN];

__device__ int g_degA[NN];      // zero-initialized; self-cleaning (scan_apply re-zeroes)
__device__ int g_offA[NN + 1];
__device__ int g_curA[NN];
__device__ int g_csrA[TOTE];

__device__ int g_degR[NN];
__device__ int g_offR[NN + 1];
__device__ int g_curR[NN];
__device__ int g_csrR[TOTE];

__device__ int g_bsum[2 * 128];
__device__ int g_boff[2 * 128];

// ================= mma.sync helpers =================
__device__ __forceinline__ uint32_t smem_u32(const void* p) {
    uint32_t a;
    asm("{ .reg .u64 t; cvta.to.shared.u64 t, %1; cvt.u32.u64 %0, t; }" : "=r"(a) : "l"(p));
    return a;
}

#define LDSM_X4(d, addr) asm volatile( \
    "ldmatrix.sync.aligned.m8n8.x4.shared.b16 {%0,%1,%2,%3}, [%4];" \
    : "=r"((d)[0]), "=r"((d)[1]), "=r"((d)[2]), "=r"((d)[3]) : "r"(addr))

#define MMA16816(c, a, b0, b1) asm volatile( \
    "mma.sync.aligned.m16n8k16.row.col.f32.bf16.bf16.f32 " \
    "{%0,%1,%2,%3}, {%4,%5,%6,%7}, {%8,%9}, {%0,%1,%2,%3};" \
    : "+f"((c)[0]), "+f"((c)[1]), "+f"((c)[2]), "+f"((c)[3]) \
    : "r"((a)[0]), "r"((a)[1]), "r"((a)[2]), "r"((a)[3]), "r"(b0), "r"(b1))

#define PITCH 136                    // bf16 elems per smem row (272 B, 16B skew)
#define SM_B_OFF (128 * PITCH * 2)   // 34816
#define SM_SC_OFF (SM_B_OFF + 64 * PITCH * 2)  // 52224
#define SM_DYN (SM_SC_OFF + 768)

// fused kernel smem layout: As | Bs1 | Bs2 | scalars
#define B_BYTES (64 * PITCH * 2)     // 17408
#define SM_B2_OFF (SM_B_OFF + B_BYTES)           // 52224
#define SM_SC2_OFF (SM_B2_OFF + B_BYTES)         // 69632
#define SM_DYN2 (SM_SC2_OFF + 768)               // 70400

// pack 4 floats -> (hi bf16 x4, lo bf16 x4) as two uint2-storable halves
__device__ __forceinline__ void cvt4(const float4& v, uint2& hi, uint2& lo) {
    __nv_bfloat162 h01 = __floats2bfloat162_rn(v.x, v.y);
    __nv_bfloat162 h23 = __floats2bfloat162_rn(v.z, v.w);
    float lx = v.x - __bfloat162float(h01.x);
    float ly = v.y - __bfloat162float(h01.y);
    float lz = v.z - __bfloat162float(h23.x);
    float lw = v.w - __bfloat162float(h23.y);
    __nv_bfloat162 l01 = __floats2bfloat162_rn(lx, ly);
    __nv_bfloat162 l23 = __floats2bfloat162_rn(lz, lw);
    hi.x = *(uint32_t*)&h01; hi.y = *(uint32_t*)&h23;
    lo.x = *(uint32_t*)&l01; lo.y = *(uint32_t*)&l23;
}

__device__ __forceinline__ void convert_A_tile(char* dsm, const float* Asrc, int row0, int n, int tid) {
    __nv_bfloat16* As = (__nv_bfloat16*)dsm;
    for (int i = tid; i < 128 * 16; i += 256) {
        int r = i >> 4, cq = (i & 15) * 4;
        int gr = row0 + r;
        float4 v = (gr < n) ? *(const float4*)(Asrc + gr * 64 + cq)
                            : make_float4(0.f, 0.f, 0.f, 0.f);
        uint2 hi, lo;
        cvt4(v, hi, lo);
        *(uint2*)(As + r * PITCH + cq) = hi;
        *(uint2*)(As + r * PITCH + 64 + cq) = lo;
    }
}

// bs points at the B tile base
__device__ __forceinline__ void convert_B_tile(char* bs_raw, const float* Wsrc, int tid) {
    __nv_bfloat16* Bs = (__nv_bfloat16*)bs_raw;
    for (int i = tid; i < 64 * 16; i += 256) {
        int k = i >> 4, nq = (i & 15) * 4;
        float4 v = *(const float4*)(Wsrc + k * 64 + nq);
        uint2 hi, lo;
        cvt4(v, hi, lo);
        __nv_bfloat162 h01 = *(__nv_bfloat162*)&hi.x;
        __nv_bfloat162 h23 = *(__nv_bfloat162*)&hi.y;
        __nv_bfloat162 l01 = *(__nv_bfloat162*)&lo.x;
        __nv_bfloat162 l23 = *(__nv_bfloat162*)&lo.y;
        Bs[(nq + 0) * PITCH + k] = h01.x;
        Bs[(nq + 1) * PITCH + k] = h01.y;
        Bs[(nq + 2) * PITCH + k] = h23.x;
        Bs[(nq + 3) * PITCH + k] = h23.y;
        Bs[(nq + 0) * PITCH + 64 + k] = l01.x;
        Bs[(nq + 1) * PITCH + 64 + k] = l01.y;
        Bs[(nq + 2) * PITCH + 64 + k] = l23.x;
        Bs[(nq + 3) * PITCH + 64 + k] = l23.y;
    }
}

// 4 k16 steps; per step load A_hi/A_lo once and per-nb B_hi/B_lo once,
// then issue hi*hi + lo*hi + hi*lo from registers (lo*lo omitted, ~2^-18)
__device__ __forceinline__ void run_mainloop(float (&acc)[8][4], uint32_t a_addr, uint32_t b_base) {
#pragma unroll
    for (int s = 0; s < 4; s++) {
        uint32_t hi_koff = (uint32_t)(s * 16) * 2;
        uint32_t lo_koff = (uint32_t)(64 + s * 16) * 2;
        uint32_t a_hi[4], a_lo[4];
        LDSM_X4(a_hi, a_addr + hi_koff);
        LDSM_X4(a_lo, a_addr + lo_koff);
#pragma unroll
        for (int nb = 0; nb < 4; nb++) {
            uint32_t b_off = b_base + (uint32_t)(nb * 16 * PITCH) * 2;
            uint32_t b_hi[4], b_lo[4];
            LDSM_X4(b_hi, b_off + hi_koff);
            LDSM_X4(b_lo, b_off + lo_koff);
            MMA16816(acc[nb * 2 + 0], a_hi, b_hi[0], b_hi[1]);
            MMA16816(acc[nb * 2 + 1], a_hi, b_hi[2], b_hi[3]);
            MMA16816(acc[nb * 2 + 0], a_lo, b_hi[0], b_hi[1]);
            MMA16816(acc[nb * 2 + 1], a_lo, b_hi[2], b_hi[3]);
            MMA16816(acc[nb * 2 + 0], a_hi, b_lo[0], b_lo[1]);
            MMA16816(acc[nb * 2 + 1], a_hi, b_lo[2], b_lo[3]);
        }
    }
}

// ================= general tensor-core GEMM (mol conv + final concat) =================
struct TcArgs {
    const float* A;
    const float* A2;      // phase-1 input (concat), else null
    const float* W;       // [K_total, 64] row-major
    const float* bias;
    const float* attS;
    const float* attD;
    float* out;
    float* as_;
    float* ad_;
    int mode;             // 1 bias, 4 att, 8 two-phase
};

__global__ void __launch_bounds__(256, 2) mma_gemm_kernel(TcArgs g0, TcArgs g1, int n) {
    extern __shared__ char dsm[];
    float* sc_bias = (float*)(dsm + SM_SC_OFF);
    float* sc_attS = sc_bias + 64;
    float* sc_attD = sc_attS + 64;

    const TcArgs g = blockIdx.y ? g1 : g0;
    int tid = threadIdx.x;
    int w = tid >> 5;
    int lane = tid & 31;
    int row0 = blockIdx.x * 128;

    if (tid < 64) sc_bias[tid] = (g.mode & 1) ? g.bias[tid] : 0.f;
    else if (tid < 128 && (g.mode & 4)) { sc_attS[tid - 64] = g.attS[tid - 64]; sc_attD[tid - 64] = g.attD[tid - 64]; }

    float acc[8][4];
#pragma unroll
    for (int ni = 0; ni < 8; ni++)
#pragma unroll
        for (int k = 0; k < 4; k++) acc[ni][k] = 0.f;

    uint32_t As_u = smem_u32(dsm);
    uint32_t Bs_u = smem_u32(dsm + SM_B_OFF);

    int a_row_local = lane & 15;
    int a_kofs = (lane >> 4) * 8;
    int b_n = (lane & 7) + ((lane >> 4) & 1) * 8;
    int b_kofs = ((lane >> 3) & 1) * 8;

    uint32_t a_addr = As_u + ((w * 16 + a_row_local) * PITCH + a_kofs) * 2;
    uint32_t b_base = Bs_u + (b_n * PITCH + b_kofs) * 2;

    int nphase = (g.mode & 8) ? 2 : 1;
    for (int ph = 0; ph < nphase; ph++) {
        const float* Asrc = ph ? g.A2 : g.A;
        const float* Wsrc = g.W + ph * 64 * 64;
        if (ph) __syncthreads();
        convert_A_tile(dsm, Asrc, row0, n, tid);
        convert_B_tile(dsm + SM_B_OFF, Wsrc, tid);
        __syncthreads();
        run_mainloop(acc, a_addr, b_base);
    }

    // ---- epilogue straight from fragments ----
    int q = lane & 3;
    int rsub = lane >> 2;
#pragma unroll
    for (int half = 0; half < 2; half++) {
        int r = row0 + w * 16 + rsub + half * 8;
        float s = 0.f, d = 0.f;
#pragma unroll
        for (int ni = 0; ni < 8; ni++) {
            int c = ni * 8 + q * 2;
            float v0 = acc[ni][half * 2 + 0] + sc_bias[c];
            float v1 = acc[ni][half * 2 + 1] + sc_bias[c + 1];
            if (g.mode & 4) {
                s += v0 * sc_attS[c] + v1 * sc_attS[c + 1];
                d += v0 * sc_attD[c] + v1 * sc_attD[c + 1];
            }
            if (r < n) {
                float2 st = {v0, v1};
                *(float2*)(g.out + r * 64 + c) = st;
            }
        }
        if (g.mode & 4) {
            s += __shfl_xor_sync(0xffffffffu, s, 1);
            s += __shfl_xor_sync(0xffffffffu, s, 2);
            d += __shfl_xor_sync(0xffffffffu, d, 1);
            d += __shfl_xor_sync(0xffffffffu, d, 2);
            if (q == 0 && r < n) { g.as_[r] = s; g.ad_[r] = d; }
        }
    }
}

// ================= fused lin1 + conv GEMM (dedicated kernel) =================
// hW = (leaky(x@W1 + b1)) @ Wc ; as_/ad_ = att dots of hW rows
// Both weight tiles are pre-converted before phase 1 (Bs1 = W1, Bs2 = Wc).
struct FusedArgs {
    const float* x;
    const float* W1;
    const float* b1;
    const float* Wc;
    const float* attS;
    const float* attD;
    float* out;
    float* as_;
    float* ad_;
};

__global__ void __launch_bounds__(256, 2) mma_fused_kernel(FusedArgs g0, FusedArgs g1, int n) {
    extern __shared__ char dsm[];
    __nv_bfloat16* As = (__nv_bfloat16*)dsm;
    float* sc_bias = (float*)(dsm + SM_SC2_OFF);
    float* sc_attS = sc_bias + 64;
    float* sc_attD = sc_attS + 64;

    const FusedArgs g = blockIdx.y ? g1 : g0;
    int tid = threadIdx.x;
    int w = tid >> 5;
    int lane = tid & 31;
    int row0 = blockIdx.x * 128;

    if (tid < 64) sc_bias[tid] = g.b1[tid];
    else if (tid < 128) { sc_attS[tid - 64] = g.attS[tid - 64]; sc_attD[tid - 64] = g.attD[tid - 64]; }

    float acc[8][4];
#pragma unroll
    for (int ni = 0; ni < 8; ni++)
#pragma unroll
        for (int k = 0; k < 4; k++) acc[ni][k] = 0.f;

    uint32_t As_u = smem_u32(dsm);
    uint32_t Bs1_u = smem_u32(dsm + SM_B_OFF);
    uint32_t Bs2_u = smem_u32(dsm + SM_B2_OFF);

    int a_row_local = lane & 15;
    int a_kofs = (lane >> 4) * 8;
    int b_n = (lane & 7) + ((lane >> 4) & 1) * 8;
    int b_kofs = ((lane >> 3) & 1) * 8;
    int q = lane & 3;
    int rsub = lane >> 2;

    uint32_t a_addr = As_u + ((w * 16 + a_row_local) * PITCH + a_kofs) * 2;
    uint32_t b1_base = Bs1_u + (b_n * PITCH + b_kofs) * 2;
    uint32_t b2_base = Bs2_u + (b_n * PITCH + b_kofs) * 2;

    // --- converts for phase 1 AND phase 2 weights, up front ---
    convert_A_tile(dsm, g.x, row0, n, tid);
    convert_B_tile(dsm + SM_B_OFF, g.W1, tid);
    convert_B_tile(dsm + SM_B2_OFF, g.Wc, tid);
    __syncthreads();

    // --- phase 1: x @ W1 ---
    run_mainloop(acc, a_addr, b1_base);

    // --- mid epilogue: v = leaky(acc + b1); re-split into As as hi/lo; zero acc ---
    __syncthreads();  // all warps done reading As
#pragma unroll
    for (int half = 0; half < 2; half++) {
        int rl = w * 16 + rsub + half * 8;
#pragma unroll
        for (int ni = 0; ni < 8; ni++) {
            int c = ni * 8 + q * 2;
            float v0 = acc[ni][half * 2 + 0] + sc_bias[c];
            float v1 = acc[ni][half * 2 + 1] + sc_bias[c + 1];
            v0 = (v0 >= 0.f) ? v0 : 0.01f * v0;
            v1 = (v1 >= 0.f) ? v1 : 0.01f * v1;
            __nv_bfloat162 hi = __floats2bfloat162_rn(v0, v1);
            float l0 = v0 - __bfloat162float(hi.x);
            float l1 = v1 - __bfloat162float(hi.y);
            __nv_bfloat162 lo = __floats2bfloat162_rn(l0, l1);
            *(__nv_bfloat162*)(As + rl * PITCH + c) = hi;
            *(__nv_bfloat162*)(As + rl * PITCH + 64 + c) = lo;
            acc[ni][half * 2 + 0] = 0.f;
            acc[ni][half * 2 + 1] = 0.f;
        }
    }
    __syncthreads();

    // --- phase 2: h @ Wc ---
    run_mainloop(acc, a_addr, b2_base);

    // --- final epilogue: store hW + att dots (no bias/act) ---
#pragma unroll
    for (int half = 0; half < 2; half++) {
        int r = row0 + w * 16 + rsub + half * 8;
        float s = 0.f, d = 0.f;
#pragma unroll
        for (int ni = 0; ni < 8; ni++) {
            int c = ni * 8 + q * 2;
            float v0 = acc[ni][half * 2 + 0];
            float v1 = acc[ni][half * 2 + 1];
            s += v0 * sc_attS[c] + v1 * sc_attS[c + 1];
            d += v0 * sc_attD[c] + v1 * sc_attD[c + 1];
            if (r < n) {
                float2 st = {v0, v1};
                *(float2*)(g.out + r * 64 + c) = st;
            }
        }
        s += __shfl_xor_sync(0xffffffffu, s, 1);
        s += __shfl_xor_sync(0xffffffffu, s, 2);
        d += __shfl_xor_sync(0xffffffffu, d, 1);
        d += __shfl_xor_sync(0xffffffffu, d, 2);
        if (q == 0 && r < n) { g.as_[r] = s; g.ad_[r] = d; }
    }
}

// ================= CSR build (merged: blockIdx.y selects graph) =================
// deg is self-cleaning: starts zero (module init / previous scan_apply), count adds,
// readers add +1 for the self loop, scan_apply zeroes after consuming.
__global__ void count_kernel(const int* dstA, const int* dstR, int* degA, int* degR) {
    int i = blockIdx.x * blockDim.x + threadIdx.x;
    const int* dst = blockIdx.y ? dstR : dstA;
    int* deg = blockIdx.y ? degR : degA;
    if (i < EE) atomicAdd(&deg[dst[i]], 1);
}
__global__ void block_sum_kernel(const int* degA, const int* degR, int* bsum) {
    __shared__ int sh[8];
    const int* deg = blockIdx.y ? degR : degA;
    int base = blockIdx.x * SCHUNK;
    int tid = threadIdx.x;
    int s = 0;
    for (int i = tid; i < SCHUNK; i += 256) {
        int idx = base + i;
        if (idx < NN) s += deg[idx] + 1;   // +1 self loop
    }
#pragma unroll
    for (int o = 16; o; o >>= 1) s += __shfl_xor_sync(0xffffffffu, s, o);
    if ((tid & 31) == 0) sh[tid >> 5] = s;
    __syncthreads();
    if (tid == 0) {
        int t = 0;
#pragma unroll
        for (int k = 0; k < 8; k++) t += sh[k];
        bsum[blockIdx.y * 128 + blockIdx.x] = t;
    }
}
__global__ void scan_sums_kernel(const int* bsum, int* boff, int* offA, int* offR) {
    __shared__ int sh[128];
    int y = blockIdx.x;
    int tid = threadIdx.x;
    int v = (tid < NB_SCAN) ? bsum[y * 128 + tid] : 0;
    sh[tid] = v;
    __syncthreads();
    for (int o = 1; o < 128; o <<= 1) {
        int t = (tid >= o) ? sh[tid - o] : 0;
        __syncthreads();
        sh[tid] += t;
        __syncthreads();
    }
    if (tid < NB_SCAN) boff[y * 128 + tid] = sh[tid] - v;
    if (tid == 127) (y ? offR : offA)[NN] = sh[127];
}
// scan_apply + fill_self merged; also zeroes deg for the next replay
__global__ void scan_apply_kernel(int* degA, int* degR, const int* boff,
                                  int* offA, int* offR, int* curA, int* curR,
                                  int* csrA, int* csrR) {
    __shared__ int wsum[8];
    int* deg = blockIdx.y ? degR : degA;
    int* off = blockIdx.y ? offR : offA;
    int* cursor = blockIdx.y ? curR : curA;
    int* csr = blockIdx.y ? csrR : csrA;
    int tid = threadIdx.x;
    int lane = tid & 31, w = tid >> 5;
    int base = blockIdx.x * SCHUNK + tid * 4;
    int v[4];
    int s = 0;
#pragma unroll
    for (int k = 0; k < 4; k++) {
        if (base + k < NN) {
            v[k] = deg[base + k] + 1;   // +1 self loop
            deg[base + k] = 0;          // reset for next replay
        } else {
            v[k] = 0;
        }
        s += v[k];
    }
    int ps = s;
#pragma unroll
    for (int o = 1; o < 32; o <<= 1) {
        int t = __shfl_up_sync(0xffffffffu, ps, o);
        if (lane >= o) ps += t;
    }
    if (lane == 31) wsum[w] = ps;
    __syncthreads();
    if (tid == 0) {
        int c = 0;
#pragma unroll
        for (int k = 0; k < 8; k++) { int t = wsum[k]; wsum[k] = c; c += t; }
    }
    __syncthreads();
    int run = boff[blockIdx.y * 128 + blockIdx.x] + wsum[w] + ps - s;
#pragma unroll
    for (int k = 0; k < 4; k++) {
        int i = base + k;
        if (i < NN) {
            off[i] = run;
            csr[run] = i;          // self loop occupies slot 0
            cursor[i] = run + 1;
        }
        run += v[k];
    }
}
__global__ void scatter_kernel(const int* srcA, const int* dstA, const int* srcR, const int* dstR,
                               int* curA, int* curR, int* csrA, int* csrR) {
    int i = blockIdx.x * blockDim.x + threadIdx.x;
    const int* src = blockIdx.y ? srcR : srcA;
    const int* dst = blockIdx.y ? dstR : dstA;
    int* cursor = blockIdx.y ? curR : curA;
    int* csr = blockIdx.y ? csrR : csrA;
    if (i < EE) {
        int p = atomicAdd(&cursor[dst[i]], 1);
        csr[p] = src[i];
    }
}

// ================= GAT aggregation (R13 best variant: dynamic inner loop) =================
struct AggArgs {
    const int* off;
    const int* csr;
    const float* hW;
    const float* as_;
    const float* ad_;
    const float* bias;
    float* out;
};
__global__ void gat_aggregate_kernel(AggArgs a0, AggArgs a1) {
    const AggArgs a = blockIdx.y ? a1 : a0;
    int warp = (blockIdx.x * blockDim.x + threadIdx.x) >> 5;
    int lane = threadIdx.x & 31;
    if (warp >= NN) return;
    int start = a.off[warp];
    int end = a.off[warp + 1];
    float adi = a.ad_[warp];

    float s = 0.f, acc0 = 0.f, acc1 = 0.f;
    for (int base = start; base < end; base += 32) {
        int j = base + lane;
        int sidx = 0;
        float ex = 0.f;
        if (j < end) {
            sidx = a.csr[j];
            float e = a.as_[sidx] + adi;
            e = (e >= 0.f) ? e : 0.2f * e;
            ex = __expf(e);
        }
        s += ex;
        int cnt = min(32, end - base);
        for (int t = 0; t < cnt; t++) {
            int ss = __shfl_sync(0xffffffffu, sidx, t);
            float w = __shfl_sync(0xffffffffu, ex, t);
            float2 v = *(const float2*)(a.hW + ss * 64 + 2 * lane);
            acc0 += w * v.x;
            acc1 += w * v.y;
        }
    }
#pragma unroll
    for (int o = 16; o; o >>= 1) s += __shfl_xor_sync(0xffffffffu, s, o);
    float inv = 1.f / (s + 1e-16f);

    float2 r;
    r.x = acc0 * inv + a.bias[2 * lane];
    r.y = acc1 * inv + a.bias[2 * lane + 1];
    *(float2*)(a.out + warp * 64 + 2 * lane) = r;
}

// ================= host launcher =================
extern "C" void kernel_launch(void* const* d_in, const int* in_sizes, int n_in,
                              void* d_out, int out_size) {
    const float* x       = (const float*)d_in[0];
    const int*   ei      = (const int*)d_in[1];
    const float* rg_x    = (const float*)d_in[3];
    const int*   rei     = (const int*)d_in[4];
    const float* W1      = (const float*)d_in[6];
    const float* b1      = (const float*)d_in[7];
    const float* atom_W  = (const float*)d_in[8];
    const float* atom_as = (const float*)d_in[9];
    const float* atom_ad = (const float*)d_in[10];
    const float* atom_b  = (const float*)d_in[11];
    const float* rg_W    = (const float*)d_in[12];
    const float* rg_as   = (const float*)d_in[13];
    const float* rg_ad   = (const float*)d_in[14];
    const float* rg_b    = (const float*)d_in[15];
    const float* mol_W   = (const float*)d_in[16];
    const float* mol_as  = (const float*)d_in[17];
    const float* mol_ad  = (const float*)d_in[18];
    const float* mol_b   = (const float*)d_in[19];
    const float* W2      = (const float*)d_in[20];
    const float* b2      = (const float*)d_in[21];
    float* out = (float*)d_out;

    const int* srcA = ei;
    const int* dstA = ei + EE;
    const int* srcR = rei;
    const int* dstR = rei + EE;

    float *hW, *hW2, *atomo, *rh, *mol, *as_, *ad_, *as2, *ad2;
    int *degA, *offA, *curA, *csrA, *degR, *offR, *curR, *csrR, *bsum, *boff;
    cudaGetSymbolAddress((void**)&hW, g_hW);
    cudaGetSymbolAddress((void**)&hW2, g_hW2);
    cudaGetSymbolAddress((void**)&atomo, g_atom);
    cudaGetSymbolAddress((void**)&rh, g_rh);
    cudaGetSymbolAddress((void**)&mol, g_mol);
    cudaGetSymbolAddress((void**)&as_, g_as);
    cudaGetSymbolAddress((void**)&ad_, g_ad);
    cudaGetSymbolAddress((void**)&as2, g_as2);
    cudaGetSymbolAddress((void**)&ad2, g_ad2);
    cudaGetSymbolAddress((void**)&degA, g_degA);
    cudaGetSymbolAddress((void**)&offA, g_offA);
    cudaGetSymbolAddress((void**)&curA, g_curA);
    cudaGetSymbolAddress((void**)&csrA, g_csrA);
    cudaGetSymbolAddress((void**)&degR, g_degR);
    cudaGetSymbolAddress((void**)&offR, g_offR);
    cudaGetSymbolAddress((void**)&curR, g_curR);
    cudaGetSymbolAddress((void**)&csrR, g_csrR);
    cudaGetSymbolAddress((void**)&bsum, g_bsum);
    cudaGetSymbolAddress((void**)&boff, g_boff);

    cudaFuncSetAttribute(mma_gemm_kernel, cudaFuncAttributeMaxDynamicSharedMemorySize, SM_DYN);
    cudaFuncSetAttribute(mma_fused_kernel, cudaFuncAttributeMaxDynamicSharedMemorySize, SM_DYN2);

    const int WB = (NN * 32 + 255) / 256;

    // CSR build (both graphs per launch); fused gemm at launch index 3 for ncu
    count_kernel<<<dim3((EE + 255) / 256, 2), 256>>>(dstA, dstR, degA, degR);
    block_sum_kernel<<<dim3(NB_SCAN, 2), 256>>>(degA, degR, bsum);
    scan_sums_kernel<<<2, 128>>>(bsum, boff, offA, offR);

    // fused lin1 + conv for both graphs (no CSR dependency)
    FusedArgs f0a = {x,    W1, b1, atom_W, atom_as, atom_ad, hW,  as_, ad_};
    FusedArgs f1a = {rg_x, W1, b1, rg_W,   rg_as,   rg_ad,   hW2, as2, ad2};
    mma_fused_kernel<<<dim3(GEMM_BLOCKS, 2), 256, SM_DYN2>>>(f0a, f1a, NN);

    scan_apply_kernel<<<dim3(NB_SCAN, 2), 256>>>(degA, degR, boff, offA, offR,
                                                 curA, curR, csrA, csrR);
    scatter_kernel<<<dim3((EE + 255) / 256, 2), 256>>>(srcA, dstA, srcR, dstR, curA, curR, csrA, csrR);

    // atom + rg aggregation
    AggArgs a0 = {offA, csrA, hW,  as_, ad_, atom_b, atomo};
    AggArgs a1 = {offR, csrR, hW2, as2, ad2, rg_b,   rh};
    gat_aggregate_kernel<<<dim3(WB, 2), 256>>>(a0, a1);

    // mol conv gemm
    TcArgs m0 = {atomo, nullptr, mol_W, nullptr, mol_as, mol_ad, hW, as_, ad_, 4};
    mma_gemm_kernel<<<dim3(GEMM_BLOCKS, 1), 256, SM_DYN>>>(m0, m0, NN);

    // mol aggregation
    AggArgs am = {offA, csrA, hW, as_, ad_, mol_b, mol};
    gat_aggregate_kernel<<<dim3(WB, 1), 256>>>(am, am);

    // final: out = concat(mol, rh) @ W2 + b2 (two-phase, bias)
    TcArgs ff = {mol, rh, W2, b2, nullptr, nullptr, out, nullptr, nullptr, 1 | 8};
    mma_gemm_kernel<<<dim3(GEMM_BLOCKS, 1), 256, SM_DYN>>>(ff, ff, NN);
}